// round 1
// baseline (speedup 1.0000x reference)
#include <cuda_runtime.h>
#include <math.h>

#define T_TOK   4096
#define H_DIM   1024
#define N_HEAD  16
#define HEAD_D  64
#define SEQ     1024
#define BATCH   4
#define F_DIM   4096
#define N_EXP   8
#define N_SLOTS (T_TOK * 2)

// ---------------- scratch (device globals; no allocation) ----------------
__device__ float g_xn[T_TOK * H_DIM];          // rmsnorm output (reused)
__device__ float g_q[T_TOK * H_DIM];
__device__ float g_k[T_TOK * H_DIM];
__device__ float g_v[T_TOK * H_DIM];
__device__ float g_ao[T_TOK * H_DIM];          // attention out (pre-WO)
__device__ float g_x1[T_TOK * H_DIM];          // x + attn residual
__device__ float g_h1[(size_t)N_SLOTS * F_DIM];// expert hidden (128 MB)
__device__ int   g_cnt[N_EXP];
__device__ int   g_fill[N_EXP];
__device__ int   g_off[N_EXP];
__device__ float g_psum[N_EXP];
__device__ int   g_topi[T_TOK * 2];
__device__ float g_topw[T_TOK * 2];
__device__ int   g_slot_tok[N_SLOTS];
__device__ float g_slot_w[N_SLOTS];

// ---------------- helpers ----------------
__device__ __forceinline__ float gelu_tanh(float x) {
    float x3 = x * x * x;
    return 0.5f * x * (1.0f + tanhf(0.7978845608028654f * (x + 0.044715f * x3)));
}

// ---------------- reset (graph-replay determinism) ----------------
__global__ void reset_kernel() {
    int i = threadIdx.x;
    if (i < N_EXP) { g_cnt[i] = 0; g_fill[i] = 0; g_psum[i] = 0.f; }
}

// ---------------- rmsnorm: one block per token ----------------
__global__ void rmsnorm_kernel(const float* __restrict__ xin,
                               const float* __restrict__ gamma,
                               int use_x1) {
    int t = blockIdx.x;
    const float* src = use_x1 ? (const float*)g_x1 : xin;
    const float4* xr = (const float4*)(src + (size_t)t * H_DIM);
    int tid = threadIdx.x;             // 256 threads, H/4 = 256 float4
    float4 v = xr[tid];
    float ss = v.x * v.x + v.y * v.y + v.z * v.z + v.w * v.w;
    // block reduce
    int lane = tid & 31, wid = tid >> 5;
    #pragma unroll
    for (int o = 16; o > 0; o >>= 1) ss += __shfl_down_sync(0xffffffffu, ss, o);
    __shared__ float red[8];
    if (lane == 0) red[wid] = ss;
    __syncthreads();
    if (tid == 0) {
        float tot = 0.f;
        #pragma unroll
        for (int i = 0; i < 8; i++) tot += red[i];
        red[0] = rsqrtf(tot / (float)H_DIM + 1e-5f);
    }
    __syncthreads();
    float r = red[0];
    float4 g = ((const float4*)gamma)[tid];
    float4 out;
    out.x = v.x * r * g.x; out.y = v.y * r * g.y;
    out.z = v.z * r * g.z; out.w = v.w * r * g.w;
    ((float4*)(g_xn + (size_t)t * H_DIM))[tid] = out;
}

// ---------------- shared 64x64x16 fp32 GEMM core ----------------
// Arow[m]: pointer to row m of A (nullptr => zeros). Bg: B + column offset.
__device__ __forceinline__ void gemm_core(const float* const (&Arow)[64],
                                          const float* __restrict__ Bg, int ldb, int K,
                                          float (&As)[16][65], float (&Bs)[16][64],
                                          float (&acc)[4][4], int tid) {
    int tx = tid & 15, ty = tid >> 4;
    for (int k0 = 0; k0 < K; k0 += 16) {
        #pragma unroll
        for (int i = 0; i < 4; i++) {
            int idx = tid + (i << 8);
            int m = idx >> 4, kk = idx & 15;
            const float* ap = Arow[m];
            As[kk][m] = ap ? ap[k0 + kk] : 0.f;
        }
        #pragma unroll
        for (int i = 0; i < 4; i++) {
            int idx = tid + (i << 8);
            int kk = idx >> 6, n = idx & 63;
            Bs[kk][n] = Bg[(size_t)(k0 + kk) * ldb + n];
        }
        __syncthreads();
        #pragma unroll
        for (int kk = 0; kk < 16; kk++) {
            float a0 = As[kk][ty * 4 + 0], a1 = As[kk][ty * 4 + 1];
            float a2 = As[kk][ty * 4 + 2], a3 = As[kk][ty * 4 + 3];
            float b0 = Bs[kk][tx * 4 + 0], b1 = Bs[kk][tx * 4 + 1];
            float b2 = Bs[kk][tx * 4 + 2], b3 = Bs[kk][tx * 4 + 3];
            acc[0][0] += a0 * b0; acc[0][1] += a0 * b1; acc[0][2] += a0 * b2; acc[0][3] += a0 * b3;
            acc[1][0] += a1 * b0; acc[1][1] += a1 * b1; acc[1][2] += a1 * b2; acc[1][3] += a1 * b3;
            acc[2][0] += a2 * b0; acc[2][1] += a2 * b1; acc[2][2] += a2 * b2; acc[2][3] += a2 * b3;
            acc[3][0] += a3 * b0; acc[3][1] += a3 * b1; acc[3][2] += a3 * b2; acc[3][3] += a3 * b3;
        }
        __syncthreads();
    }
}

// ---------------- QKV projection: grid.z selects weight/output ----------------
__global__ void gemm_qkv_kernel(const float* __restrict__ wq,
                                const float* __restrict__ wk,
                                const float* __restrict__ wv) {
    __shared__ const float* Arow[64];
    __shared__ float As[16][65];
    __shared__ float Bs[16][64];
    int tid = threadIdx.x;
    int nb = blockIdx.x * 64, mb = blockIdx.y * 64;
    const float* B = (blockIdx.z == 0 ? wq : (blockIdx.z == 1 ? wk : wv)) + nb;
    float* C = (blockIdx.z == 0 ? g_q : (blockIdx.z == 1 ? g_k : g_v));
    if (tid < 64) Arow[tid] = g_xn + (size_t)(mb + tid) * H_DIM;
    __syncthreads();
    float acc[4][4] = {};
    gemm_core(Arow, B, H_DIM, H_DIM, As, Bs, acc, tid);
    int tx = tid & 15, ty = tid >> 4;
    #pragma unroll
    for (int i = 0; i < 4; i++)
        #pragma unroll
        for (int j = 0; j < 4; j++)
            C[(size_t)(mb + ty * 4 + i) * H_DIM + nb + tx * 4 + j] = acc[i][j];
}

// ---------------- RoPE (in-place on g_q, g_k) ----------------
__global__ void rope_kernel() {
    int gid = blockIdx.x * blockDim.x + threadIdx.x;
    if (gid >= T_TOK * N_HEAD * 32) return;
    int i = gid & 31;
    int n = (gid >> 5) & 15;
    int t = gid >> 9;
    int s = t & (SEQ - 1);
    float inv = __expf(-9.210340371976184f * ((float)i / 32.0f)); // 10000^{-i/32}
    float ang = (float)s * inv;
    float c = cosf(ang), si = sinf(ang);
    size_t base = (size_t)t * H_DIM + n * HEAD_D;
    {
        float x1 = g_q[base + i], x2 = g_q[base + 32 + i];
        g_q[base + i]      = x1 * c - x2 * si;
        g_q[base + 32 + i] = x2 * c + x1 * si;
    }
    {
        float x1 = g_k[base + i], x2 = g_k[base + 32 + i];
        g_k[base + i]      = x1 * c - x2 * si;
        g_k[base + 32 + i] = x2 * c + x1 * si;
    }
}

// ---------------- flash attention: 64 threads, 1 query row per thread ----------------
__global__ void flash_kernel() {
    __shared__ float Ks[64][64];
    __shared__ float Vs[64][64];
    int qt = blockIdx.x, nh = blockIdx.y, b = blockIdx.z;
    int tid = threadIdx.x; // 64
    int qrow = qt * 64 + tid;
    int t = b * SEQ + qrow;
    float q[64], o[64];
    const float4* qp = (const float4*)(g_q + (size_t)t * H_DIM + nh * HEAD_D);
    #pragma unroll
    for (int i = 0; i < 16; i++) {
        float4 v = qp[i];
        q[4 * i] = v.x; q[4 * i + 1] = v.y; q[4 * i + 2] = v.z; q[4 * i + 3] = v.w;
    }
    #pragma unroll
    for (int d = 0; d < 64; d++) o[d] = 0.f;
    float m = -1e30f, l = 0.f;
    for (int kt = 0; kt <= qt; kt++) {
        // cooperative coalesced K/V tile load (thread = column)
        for (int r = 0; r < 64; r++) {
            size_t src = (size_t)(b * SEQ + kt * 64 + r) * H_DIM + nh * HEAD_D + tid;
            Ks[r][tid] = g_k[src];
            Vs[r][tid] = g_v[src];
        }
        __syncthreads();
        for (int j = 0; j < 64; j++) {
            int kglob = kt * 64 + j;
            if (kglob > qrow) break;
            float s0 = 0.f, s1 = 0.f, s2 = 0.f, s3 = 0.f;
            #pragma unroll
            for (int d = 0; d < 64; d += 4) {
                s0 += q[d]     * Ks[j][d];
                s1 += q[d + 1] * Ks[j][d + 1];
                s2 += q[d + 2] * Ks[j][d + 2];
                s3 += q[d + 3] * Ks[j][d + 3];
            }
            float s = (s0 + s1 + s2 + s3) * 0.125f;
            if (s > m) {
                float c = __expf(m - s);
                l *= c;
                #pragma unroll
                for (int d = 0; d < 64; d++) o[d] *= c;
                m = s;
            }
            float p = __expf(s - m);
            l += p;
            #pragma unroll
            for (int d = 0; d < 64; d++) o[d] += p * Vs[j][d];
        }
        __syncthreads();
    }
    float invl = 1.0f / l;
    float* op = g_ao + (size_t)t * H_DIM + nh * HEAD_D;
    #pragma unroll
    for (int d = 0; d < 64; d++) op[d] = o[d] * invl;
}

// ---------------- WO projection + residual; writes g_x1 AND d_out ----------------
__global__ void gemm_wo_kernel(const float* __restrict__ x,
                               const float* __restrict__ wo,
                               float* __restrict__ dout) {
    __shared__ const float* Arow[64];
    __shared__ float As[16][65];
    __shared__ float Bs[16][64];
    int tid = threadIdx.x;
    int nb = blockIdx.x * 64, mb = blockIdx.y * 64;
    if (tid < 64) Arow[tid] = g_ao + (size_t)(mb + tid) * H_DIM;
    __syncthreads();
    float acc[4][4] = {};
    gemm_core(Arow, wo + nb, H_DIM, H_DIM, As, Bs, acc, tid);
    int tx = tid & 15, ty = tid >> 4;
    #pragma unroll
    for (int i = 0; i < 4; i++)
        #pragma unroll
        for (int j = 0; j < 4; j++) {
            size_t idx = (size_t)(mb + ty * 4 + i) * H_DIM + nb + tx * 4 + j;
            float v = x[idx] + acc[i][j];
            g_x1[idx] = v;
            dout[idx] = v;
        }
}

// ---------------- router: 1 warp per token ----------------
__global__ void router_kernel(const float* __restrict__ wr) {
    int warp = (blockIdx.x * blockDim.x + threadIdx.x) >> 5;
    int lane = threadIdx.x & 31;
    if (warp >= T_TOK) return;
    const float* xr = g_xn + (size_t)warp * H_DIM;
    float acc[N_EXP];
    #pragma unroll
    for (int e = 0; e < N_EXP; e++) acc[e] = 0.f;
    for (int h = lane; h < H_DIM; h += 32) {
        float xv = xr[h];
        #pragma unroll
        for (int e = 0; e < N_EXP; e++) acc[e] += xv * wr[h * N_EXP + e];
    }
    #pragma unroll
    for (int e = 0; e < N_EXP; e++)
        #pragma unroll
        for (int o = 16; o > 0; o >>= 1)
            acc[e] += __shfl_down_sync(0xffffffffu, acc[e], o);
    if (lane == 0) {
        float mx = acc[0];
        #pragma unroll
        for (int e = 1; e < N_EXP; e++) mx = fmaxf(mx, acc[e]);
        float p[N_EXP], s = 0.f;
        #pragma unroll
        for (int e = 0; e < N_EXP; e++) { p[e] = expf(acc[e] - mx); s += p[e]; }
        float invs = 1.0f / s;
        #pragma unroll
        for (int e = 0; e < N_EXP; e++) p[e] *= invs;
        int i0 = 0;
        #pragma unroll
        for (int e = 1; e < N_EXP; e++) if (p[e] > p[i0]) i0 = e;
        int i1 = (i0 == 0) ? 1 : 0;
        #pragma unroll
        for (int e = 0; e < N_EXP; e++) if (e != i0 && p[e] > p[i1]) i1 = e;
        float w0 = p[i0], w1 = p[i1];
        float ws = 1.0f / (w0 + w1);
        g_topi[warp * 2] = i0;     g_topi[warp * 2 + 1] = i1;
        g_topw[warp * 2] = w0 * ws; g_topw[warp * 2 + 1] = w1 * ws;
        atomicAdd(&g_cnt[i0], 1);
        atomicAdd(&g_cnt[i1], 1);
        #pragma unroll
        for (int e = 0; e < N_EXP; e++) atomicAdd(&g_psum[e], p[e]);
    }
}

// ---------------- prefix over expert counts + aux loss ----------------
__global__ void scan_kernel(float* __restrict__ dout, int write_aux) {
    if (threadIdx.x == 0) {
        int off = 0;
        float aux = 0.f;
        for (int e = 0; e < N_EXP; e++) { g_off[e] = off; off += g_cnt[e]; }
        for (int e = 0; e < N_EXP; e++) {
            float f = (float)g_cnt[e] / (float)(T_TOK * 2);
            float P = g_psum[e] / (float)T_TOK;
            aux += f * P;
        }
        aux *= (float)N_EXP;
        if (write_aux) dout[(size_t)T_TOK * H_DIM] = aux;
    }
}

// ---------------- build gather lists ----------------
__global__ void fill_kernel() {
    int gid = blockIdx.x * blockDim.x + threadIdx.x;
    if (gid >= T_TOK * 2) return;
    int t = gid >> 1;
    int e = g_topi[gid];
    int pos = g_off[e] + atomicAdd(&g_fill[e], 1);
    g_slot_tok[pos] = t;
    g_slot_w[pos] = g_topw[gid];
}

// ---------------- MoE GEMM1: h1 = gelu(xn2 @ w1[e]) (gathered) ----------------
__global__ void moe_gemm1_kernel(const float* __restrict__ w1) {
    int e = blockIdx.z;
    int cnt = g_cnt[e];
    int mt = blockIdx.y;
    if (mt * 64 >= cnt) return;
    int off = g_off[e];
    __shared__ const float* Arow[64];
    __shared__ float As[16][65];
    __shared__ float Bs[16][64];
    int tid = threadIdx.x;
    if (tid < 64) {
        int rl = mt * 64 + tid;
        Arow[tid] = (rl < cnt) ? g_xn + (size_t)g_slot_tok[off + rl] * H_DIM : (const float*)0;
    }
    __syncthreads();
    int nb = blockIdx.x * 64;
    const float* B = w1 + (size_t)e * H_DIM * F_DIM + nb;
    float acc[4][4] = {};
    gemm_core(Arow, B, F_DIM, H_DIM, As, Bs, acc, tid);
    int tx = tid & 15, ty = tid >> 4;
    #pragma unroll
    for (int i = 0; i < 4; i++) {
        int rl = mt * 64 + ty * 4 + i;
        if (rl >= cnt) continue;
        #pragma unroll
        for (int j = 0; j < 4; j++)
            g_h1[(size_t)(off + rl) * F_DIM + nb + tx * 4 + j] = gelu_tanh(acc[i][j]);
    }
}

// ---------------- MoE GEMM2: out += w * (h1 @ w2[e]) (scatter-add) ----------------
__global__ void moe_gemm2_kernel(const float* __restrict__ w2,
                                 float* __restrict__ dout) {
    int e = blockIdx.z;
    int cnt = g_cnt[e];
    int mt = blockIdx.y;
    if (mt * 64 >= cnt) return;
    int off = g_off[e];
    __shared__ const float* Arow[64];
    __shared__ float As[16][65];
    __shared__ float Bs[16][64];
    int tid = threadIdx.x;
    if (tid < 64) {
        int rl = mt * 64 + tid;
        Arow[tid] = (rl < cnt) ? g_h1 + (size_t)(off + rl) * F_DIM : (const float*)0;
    }
    __syncthreads();
    int nb = blockIdx.x * 64;
    const float* B = w2 + (size_t)e * F_DIM * H_DIM + nb;
    float acc[4][4] = {};
    gemm_core(Arow, B, H_DIM, F_DIM, As, Bs, acc, tid);
    int tx = tid & 15, ty = tid >> 4;
    #pragma unroll
    for (int i = 0; i < 4; i++) {
        int rl = mt * 64 + ty * 4 + i;
        if (rl >= cnt) continue;
        int tok = g_slot_tok[off + rl];
        float w = g_slot_w[off + rl];
        #pragma unroll
        for (int j = 0; j < 4; j++)
            atomicAdd(&dout[(size_t)tok * H_DIM + nb + tx * 4 + j], w * acc[i][j]);
    }
}

// ---------------- launch ----------------
extern "C" void kernel_launch(void* const* d_in, const int* in_sizes, int n_in,
                              void* d_out, int out_size) {
    const float* x     = (const float*)d_in[0];
    const float* gattn = (const float*)d_in[1];
    const float* wq    = (const float*)d_in[2];
    const float* wk    = (const float*)d_in[3];
    const float* wv    = (const float*)d_in[4];
    const float* wo    = (const float*)d_in[5];
    const float* gffn  = (const float*)d_in[6];
    const float* wr    = (const float*)d_in[7];
    const float* w1    = (const float*)d_in[8];
    const float* w2    = (const float*)d_in[9];
    float* out = (float*)d_out;
    int write_aux = (out_size > T_TOK * H_DIM) ? 1 : 0;

    reset_kernel<<<1, 32>>>();

    // attention block
    rmsnorm_kernel<<<T_TOK, 256>>>(x, gattn, 0);
    {
        dim3 g(H_DIM / 64, T_TOK / 64, 3);
        gemm_qkv_kernel<<<g, 256>>>(wq, wk, wv);
    }
    {
        int nthr = T_TOK * N_HEAD * 32;
        rope_kernel<<<(nthr + 255) / 256, 256>>>();
    }
    {
        dim3 g(SEQ / 64, N_HEAD, BATCH);
        flash_kernel<<<g, 64>>>();
    }
    {
        dim3 g(H_DIM / 64, T_TOK / 64);
        gemm_wo_kernel<<<g, 256>>>(x, wo, out);
    }

    // MoE block
    rmsnorm_kernel<<<T_TOK, 256>>>(x, gffn, 1);
    router_kernel<<<T_TOK / 4, 128>>>(wr);
    scan_kernel<<<1, 32>>>(out, write_aux);
    fill_kernel<<<(T_TOK * 2 + 255) / 256, 256>>>();
    {
        dim3 g(F_DIM / 64, T_TOK / 64, N_EXP);
        moe_gemm1_kernel<<<g, 256>>>(w1);
    }
    {
        dim3 g(H_DIM / 64, T_TOK / 64, N_EXP);
        moe_gemm2_kernel<<<g, 256>>>(w2, out);
    }
}

// round 3
// speedup vs baseline: 2.1684x; 2.1684x over previous
#include <cuda_runtime.h>
#include <math.h>
#include <stdint.h>

#define T_TOK   4096
#define H_DIM   1024
#define N_HEAD  16
#define HEAD_D  64
#define SEQ     1024
#define BATCH   4
#define F_DIM   4096
#define N_EXP   8
#define N_SLOTS (T_TOK * 2)

// ---------------- scratch (device globals; no allocation) ----------------
__device__ float g_xn[T_TOK * H_DIM];
__device__ float g_q[T_TOK * H_DIM];
__device__ float g_k[T_TOK * H_DIM];
__device__ float g_v[T_TOK * H_DIM];
__device__ float g_ao[T_TOK * H_DIM];
__device__ float g_x1[T_TOK * H_DIM];
__device__ float g_h1[(size_t)N_SLOTS * F_DIM];
__device__ int   g_cnt[N_EXP];
__device__ int   g_fill[N_EXP];
__device__ int   g_off[N_EXP];
__device__ float g_psum[N_EXP];
__device__ int   g_topi[T_TOK * 2];
__device__ float g_topw[T_TOK * 2];
__device__ int   g_slot_tok[N_SLOTS];
__device__ float g_slot_w[N_SLOTS];

// ---------------- helpers ----------------
__device__ __forceinline__ float gelu_tanh(float x) {
    float x3 = x * x * x;
    return 0.5f * x * (1.0f + tanhf(0.7978845608028654f * (x + 0.044715f * x3)));
}

__device__ __forceinline__ uint32_t f2tf(float f) {
    uint32_t r;
    asm("cvt.rna.tf32.f32 %0, %1;" : "=r"(r) : "f"(f));
    return r;
}

__device__ __forceinline__ void mma_tf32(float (&c)[4], const uint32_t (&a)[4],
                                         const uint32_t (&b)[2]) {
    asm volatile(
        "mma.sync.aligned.m16n8k8.row.col.f32.tf32.tf32.f32 "
        "{%0,%1,%2,%3}, {%4,%5,%6,%7}, {%8,%9}, {%0,%1,%2,%3};"
        : "+f"(c[0]), "+f"(c[1]), "+f"(c[2]), "+f"(c[3])
        : "r"(a[0]), "r"(a[1]), "r"(a[2]), "r"(a[3]), "r"(b[0]), "r"(b[1]));
}

// ---------------- reset ----------------
__global__ void reset_kernel() {
    int i = threadIdx.x;
    if (i < N_EXP) { g_cnt[i] = 0; g_fill[i] = 0; g_psum[i] = 0.f; }
}

// ---------------- rmsnorm ----------------
__global__ void rmsnorm_kernel(const float* __restrict__ xin,
                               const float* __restrict__ gamma,
                               int use_x1) {
    int t = blockIdx.x;
    const float* src = use_x1 ? (const float*)g_x1 : xin;
    const float4* xr = (const float4*)(src + (size_t)t * H_DIM);
    int tid = threadIdx.x;
    float4 v = xr[tid];
    float ss = v.x * v.x + v.y * v.y + v.z * v.z + v.w * v.w;
    int lane = tid & 31, wid = tid >> 5;
    #pragma unroll
    for (int o = 16; o > 0; o >>= 1) ss += __shfl_down_sync(0xffffffffu, ss, o);
    __shared__ float red[8];
    if (lane == 0) red[wid] = ss;
    __syncthreads();
    if (tid == 0) {
        float tot = 0.f;
        #pragma unroll
        for (int i = 0; i < 8; i++) tot += red[i];
        red[0] = rsqrtf(tot / (float)H_DIM + 1e-5f);
    }
    __syncthreads();
    float r = red[0];
    float4 g = ((const float4*)gamma)[tid];
    float4 out;
    out.x = v.x * r * g.x; out.y = v.y * r * g.y;
    out.z = v.z * r * g.z; out.w = v.w * r * g.w;
    ((float4*)(g_xn + (size_t)t * H_DIM))[tid] = out;
}

// =====================================================================
// tf32 tensor-core GEMM core: 64x64 block tile, BK=16, 128 threads.
// 4 warps in 2x2; warp tile 32x32 = 2 m16-tiles x 4 n8-tiles (m16n8k8).
// As stride 20 floats (banks 4m+k conflict-free), Bs stride 72 (8k+n).
// Register prefetch of the next k-chunk overlaps global latency.
// =====================================================================
#define AS_STRIDE 20
#define BS_STRIDE 72

__device__ __forceinline__ void gemm_tf32_core(
    const float* const (&Arow)[64], const float* __restrict__ B, int ldb, int K,
    uint32_t (&As)[64][AS_STRIDE], uint32_t (&Bs)[16][BS_STRIDE],
    float (&acc)[2][4][4], int tid)
{
    const int ar = tid >> 1, ac = (tid & 1) * 8;     // A: row, col-base (8 floats)
    const int bk = tid >> 3, bn = (tid & 7) * 8;     // B: k-row, n-base (8 floats)
    const int lane = tid & 31, warp = tid >> 5;
    const int wm = warp >> 1, wn = warp & 1;
    const int lq = lane >> 2, kq = lane & 3;

    float4 ra0, ra1, rb0, rb1;
    {
        const float* ap = Arow[ar];
        if (ap) { ra0 = *(const float4*)(ap + ac); ra1 = *(const float4*)(ap + ac + 4); }
        else    { ra0 = make_float4(0.f,0.f,0.f,0.f); ra1 = ra0; }
        const float* bp = B + (size_t)bk * ldb + bn;
        rb0 = *(const float4*)bp; rb1 = *(const float4*)(bp + 4);
    }

    for (int k0 = 0; k0 < K; k0 += 16) {
        // store prefetched chunk to smem (convert to tf32)
        As[ar][ac + 0] = f2tf(ra0.x); As[ar][ac + 1] = f2tf(ra0.y);
        As[ar][ac + 2] = f2tf(ra0.z); As[ar][ac + 3] = f2tf(ra0.w);
        As[ar][ac + 4] = f2tf(ra1.x); As[ar][ac + 5] = f2tf(ra1.y);
        As[ar][ac + 6] = f2tf(ra1.z); As[ar][ac + 7] = f2tf(ra1.w);
        Bs[bk][bn + 0] = f2tf(rb0.x); Bs[bk][bn + 1] = f2tf(rb0.y);
        Bs[bk][bn + 2] = f2tf(rb0.z); Bs[bk][bn + 3] = f2tf(rb0.w);
        Bs[bk][bn + 4] = f2tf(rb1.x); Bs[bk][bn + 5] = f2tf(rb1.y);
        Bs[bk][bn + 6] = f2tf(rb1.z); Bs[bk][bn + 7] = f2tf(rb1.w);
        __syncthreads();

        // prefetch next chunk while computing this one
        if (k0 + 16 < K) {
            const float* ap = Arow[ar];
            if (ap) {
                ra0 = *(const float4*)(ap + k0 + 16 + ac);
                ra1 = *(const float4*)(ap + k0 + 16 + ac + 4);
            } else { ra0 = make_float4(0.f,0.f,0.f,0.f); ra1 = ra0; }
            const float* bp = B + (size_t)(k0 + 16 + bk) * ldb + bn;
            rb0 = *(const float4*)bp; rb1 = *(const float4*)(bp + 4);
        }

        #pragma unroll
        for (int ks = 0; ks < 2; ks++) {
            uint32_t a[2][4], b[4][2];
            #pragma unroll
            for (int mt = 0; mt < 2; mt++) {
                int r = wm * 32 + mt * 16 + lq;
                a[mt][0] = As[r    ][ks * 8 + kq];
                a[mt][1] = As[r + 8][ks * 8 + kq];
                a[mt][2] = As[r    ][ks * 8 + kq + 4];
                a[mt][3] = As[r + 8][ks * 8 + kq + 4];
            }
            #pragma unroll
            for (int nt = 0; nt < 4; nt++) {
                int c = wn * 32 + nt * 8 + lq;
                b[nt][0] = Bs[ks * 8 + kq    ][c];
                b[nt][1] = Bs[ks * 8 + kq + 4][c];
            }
            #pragma unroll
            for (int mt = 0; mt < 2; mt++)
                #pragma unroll
                for (int nt = 0; nt < 4; nt++)
                    mma_tf32(acc[mt][nt], a[mt], b[nt]);
        }
        __syncthreads();
    }
}

// ---------------- QKV projection ----------------
__global__ void gemm_qkv_kernel(const float* __restrict__ wq,
                                const float* __restrict__ wk,
                                const float* __restrict__ wv) {
    __shared__ const float* Arow[64];
    __shared__ uint32_t As[64][AS_STRIDE];
    __shared__ uint32_t Bs[16][BS_STRIDE];
    int tid = threadIdx.x;
    int nb = blockIdx.x * 64, mb = blockIdx.y * 64;
    const float* B = (blockIdx.z == 0 ? wq : (blockIdx.z == 1 ? wk : wv)) + nb;
    float* C = (blockIdx.z == 0 ? g_q : (blockIdx.z == 1 ? g_k : g_v));
    if (tid < 64) Arow[tid] = g_xn + (size_t)(mb + tid) * H_DIM;
    __syncthreads();
    float acc[2][4][4] = {};
    gemm_tf32_core(Arow, B, H_DIM, H_DIM, As, Bs, acc, tid);
    int lane = tid & 31, warp = tid >> 5;
    int wm = warp >> 1, wn = warp & 1;
    int lq = lane >> 2, kq = lane & 3;
    #pragma unroll
    for (int mt = 0; mt < 2; mt++) {
        int r0 = mb + wm * 32 + mt * 16 + lq;
        #pragma unroll
        for (int nt = 0; nt < 4; nt++) {
            int c0 = nb + wn * 32 + nt * 8 + 2 * kq;
            C[(size_t)r0 * H_DIM + c0]           = acc[mt][nt][0];
            C[(size_t)r0 * H_DIM + c0 + 1]       = acc[mt][nt][1];
            C[(size_t)(r0 + 8) * H_DIM + c0]     = acc[mt][nt][2];
            C[(size_t)(r0 + 8) * H_DIM + c0 + 1] = acc[mt][nt][3];
        }
    }
}

// ---------------- RoPE ----------------
__global__ void rope_kernel() {
    int gid = blockIdx.x * blockDim.x + threadIdx.x;
    if (gid >= T_TOK * N_HEAD * 32) return;
    int i = gid & 31;
    int n = (gid >> 5) & 15;
    int t = gid >> 9;
    int s = t & (SEQ - 1);
    float inv = __expf(-9.210340371976184f * ((float)i / 32.0f));
    float ang = (float)s * inv;
    float c = cosf(ang), si = sinf(ang);
    size_t base = (size_t)t * H_DIM + n * HEAD_D;
    {
        float x1 = g_q[base + i], x2 = g_q[base + 32 + i];
        g_q[base + i]      = x1 * c - x2 * si;
        g_q[base + 32 + i] = x2 * c + x1 * si;
    }
    {
        float x1 = g_k[base + i], x2 = g_k[base + 32 + i];
        g_k[base + i]      = x1 * c - x2 * si;
        g_k[base + 32 + i] = x2 * c + x1 * si;
    }
}

// ---------------- flash attention ----------------
__global__ void flash_kernel() {
    __shared__ float Ks[64][64];
    __shared__ float Vs[64][64];
    int qt = blockIdx.x, nh = blockIdx.y, b = blockIdx.z;
    int tid = threadIdx.x;
    int qrow = qt * 64 + tid;
    int t = b * SEQ + qrow;
    float q[64], o[64];
    const float4* qp = (const float4*)(g_q + (size_t)t * H_DIM + nh * HEAD_D);
    #pragma unroll
    for (int i = 0; i < 16; i++) {
        float4 v = qp[i];
        q[4 * i] = v.x; q[4 * i + 1] = v.y; q[4 * i + 2] = v.z; q[4 * i + 3] = v.w;
    }
    #pragma unroll
    for (int d = 0; d < 64; d++) o[d] = 0.f;
    float m = -1e30f, l = 0.f;
    for (int kt = 0; kt <= qt; kt++) {
        for (int r = 0; r < 64; r++) {
            size_t src = (size_t)(b * SEQ + kt * 64 + r) * H_DIM + nh * HEAD_D + tid;
            Ks[r][tid] = g_k[src];
            Vs[r][tid] = g_v[src];
        }
        __syncthreads();
        for (int j = 0; j < 64; j++) {
            int kglob = kt * 64 + j;
            if (kglob > qrow) break;
            float s0 = 0.f, s1 = 0.f, s2 = 0.f, s3 = 0.f;
            #pragma unroll
            for (int d = 0; d < 64; d += 4) {
                s0 += q[d]     * Ks[j][d];
                s1 += q[d + 1] * Ks[j][d + 1];
                s2 += q[d + 2] * Ks[j][d + 2];
                s3 += q[d + 3] * Ks[j][d + 3];
            }
            float s = (s0 + s1 + s2 + s3) * 0.125f;
            if (s > m) {
                float c = __expf(m - s);
                l *= c;
                #pragma unroll
                for (int d = 0; d < 64; d++) o[d] *= c;
                m = s;
            }
            float p = __expf(s - m);
            l += p;
            #pragma unroll
            for (int d = 0; d < 64; d++) o[d] += p * Vs[j][d];
        }
        __syncthreads();
    }
    float invl = 1.0f / l;
    float* op = g_ao + (size_t)t * H_DIM + nh * HEAD_D;
    #pragma unroll
    for (int d = 0; d < 64; d++) op[d] = o[d] * invl;
}

// ---------------- WO projection + residual ----------------
__global__ void gemm_wo_kernel(const float* __restrict__ x,
                               const float* __restrict__ wo,
                               float* __restrict__ dout) {
    __shared__ const float* Arow[64];
    __shared__ uint32_t As[64][AS_STRIDE];
    __shared__ uint32_t Bs[16][BS_STRIDE];
    int tid = threadIdx.x;
    int nb = blockIdx.x * 64, mb = blockIdx.y * 64;
    if (tid < 64) Arow[tid] = g_ao + (size_t)(mb + tid) * H_DIM;
    __syncthreads();
    float acc[2][4][4] = {};
    gemm_tf32_core(Arow, wo + nb, H_DIM, H_DIM, As, Bs, acc, tid);
    int lane = tid & 31, warp = tid >> 5;
    int wm = warp >> 1, wn = warp & 1;
    int lq = lane >> 2, kq = lane & 3;
    #pragma unroll
    for (int mt = 0; mt < 2; mt++) {
        int r0 = mb + wm * 32 + mt * 16 + lq;
        #pragma unroll
        for (int nt = 0; nt < 4; nt++) {
            int c0 = nb + wn * 32 + nt * 8 + 2 * kq;
            #pragma unroll
            for (int h = 0; h < 2; h++) {
                size_t i0 = (size_t)(r0 + h * 8) * H_DIM + c0;
                float v0 = x[i0] + acc[mt][nt][h * 2];
                float v1 = x[i0 + 1] + acc[mt][nt][h * 2 + 1];
                g_x1[i0] = v0; g_x1[i0 + 1] = v1;
                dout[i0] = v0; dout[i0 + 1] = v1;
            }
        }
    }
}

// ---------------- router ----------------
__global__ void router_kernel(const float* __restrict__ wr) {
    int warp = (blockIdx.x * blockDim.x + threadIdx.x) >> 5;
    int lane = threadIdx.x & 31;
    if (warp >= T_TOK) return;
    const float* xr = g_xn + (size_t)warp * H_DIM;
    float acc[N_EXP];
    #pragma unroll
    for (int e = 0; e < N_EXP; e++) acc[e] = 0.f;
    for (int h = lane; h < H_DIM; h += 32) {
        float xv = xr[h];
        #pragma unroll
        for (int e = 0; e < N_EXP; e++) acc[e] += xv * wr[h * N_EXP + e];
    }
    #pragma unroll
    for (int e = 0; e < N_EXP; e++)
        #pragma unroll
        for (int o = 16; o > 0; o >>= 1)
            acc[e] += __shfl_down_sync(0xffffffffu, acc[e], o);
    if (lane == 0) {
        float mx = acc[0];
        #pragma unroll
        for (int e = 1; e < N_EXP; e++) mx = fmaxf(mx, acc[e]);
        float p[N_EXP], s = 0.f;
        #pragma unroll
        for (int e = 0; e < N_EXP; e++) { p[e] = expf(acc[e] - mx); s += p[e]; }
        float invs = 1.0f / s;
        #pragma unroll
        for (int e = 0; e < N_EXP; e++) p[e] *= invs;
        int i0 = 0;
        #pragma unroll
        for (int e = 1; e < N_EXP; e++) if (p[e] > p[i0]) i0 = e;
        int i1 = (i0 == 0) ? 1 : 0;
        #pragma unroll
        for (int e = 0; e < N_EXP; e++) if (e != i0 && p[e] > p[i1]) i1 = e;
        float w0 = p[i0], w1 = p[i1];
        float ws = 1.0f / (w0 + w1);
        g_topi[warp * 2] = i0;      g_topi[warp * 2 + 1] = i1;
        g_topw[warp * 2] = w0 * ws; g_topw[warp * 2 + 1] = w1 * ws;
        atomicAdd(&g_cnt[i0], 1);
        atomicAdd(&g_cnt[i1], 1);
        #pragma unroll
        for (int e = 0; e < N_EXP; e++) atomicAdd(&g_psum[e], p[e]);
    }
}

// ---------------- prefix + aux ----------------
__global__ void scan_kernel(float* __restrict__ dout, int write_aux) {
    if (threadIdx.x == 0) {
        int off = 0;
        float aux = 0.f;
        for (int e = 0; e < N_EXP; e++) { g_off[e] = off; off += g_cnt[e]; }
        for (int e = 0; e < N_EXP; e++) {
            float f = (float)g_cnt[e] / (float)(T_TOK * 2);
            float P = g_psum[e] / (float)T_TOK;
            aux += f * P;
        }
        aux *= (float)N_EXP;
        if (write_aux) dout[(size_t)T_TOK * H_DIM] = aux;
    }
}

// ---------------- gather lists ----------------
__global__ void fill_kernel() {
    int gid = blockIdx.x * blockDim.x + threadIdx.x;
    if (gid >= T_TOK * 2) return;
    int t = gid >> 1;
    int e = g_topi[gid];
    int pos = g_off[e] + atomicAdd(&g_fill[e], 1);
    g_slot_tok[pos] = t;
    g_slot_w[pos] = g_topw[gid];
}

// ---------------- MoE GEMM1 ----------------
__global__ void moe_gemm1_kernel(const float* __restrict__ w1) {
    int e = blockIdx.z;
    int cnt = g_cnt[e];
    int mt_ = blockIdx.y;
    if (mt_ * 64 >= cnt) return;
    int off = g_off[e];
    __shared__ const float* Arow[64];
    __shared__ uint32_t As[64][AS_STRIDE];
    __shared__ uint32_t Bs[16][BS_STRIDE];
    int tid = threadIdx.x;
    if (tid < 64) {
        int rl = mt_ * 64 + tid;
        Arow[tid] = (rl < cnt) ? g_xn + (size_t)g_slot_tok[off + rl] * H_DIM : (const float*)0;
    }
    __syncthreads();
    int nb = blockIdx.x * 64;
    const float* B = w1 + (size_t)e * H_DIM * F_DIM + nb;
    float acc[2][4][4] = {};
    gemm_tf32_core(Arow, B, F_DIM, H_DIM, As, Bs, acc, tid);
    int lane = tid & 31, warp = tid >> 5;
    int wm = warp >> 1, wn = warp & 1;
    int lq = lane >> 2, kq = lane & 3;
    #pragma unroll
    for (int mt = 0; mt < 2; mt++) {
        #pragma unroll
        for (int h = 0; h < 2; h++) {
            int rl = mt_ * 64 + wm * 32 + mt * 16 + lq + h * 8;
            if (rl >= cnt) continue;
            float* dst = g_h1 + (size_t)(off + rl) * F_DIM + nb;
            #pragma unroll
            for (int nt = 0; nt < 4; nt++) {
                int c0 = wn * 32 + nt * 8 + 2 * kq;
                dst[c0]     = gelu_tanh(acc[mt][nt][h * 2]);
                dst[c0 + 1] = gelu_tanh(acc[mt][nt][h * 2 + 1]);
            }
        }
    }
}

// ---------------- MoE GEMM2 ----------------
__global__ void moe_gemm2_kernel(const float* __restrict__ w2,
                                 float* __restrict__ dout) {
    int e = blockIdx.z;
    int cnt = g_cnt[e];
    int mt_ = blockIdx.y;
    if (mt_ * 64 >= cnt) return;
    int off = g_off[e];
    __shared__ const float* Arow[64];
    __shared__ uint32_t As[64][AS_STRIDE];
    __shared__ uint32_t Bs[16][BS_STRIDE];
    int tid = threadIdx.x;
    if (tid < 64) {
        int rl = mt_ * 64 + tid;
        Arow[tid] = (rl < cnt) ? g_h1 + (size_t)(off + rl) * F_DIM : (const float*)0;
    }
    __syncthreads();
    int nb = blockIdx.x * 64;
    const float* B = w2 + (size_t)e * F_DIM * H_DIM + nb;
    float acc[2][4][4] = {};
    gemm_tf32_core(Arow, B, H_DIM, F_DIM, As, Bs, acc, tid);
    int lane = tid & 31, warp = tid >> 5;
    int wm = warp >> 1, wn = warp & 1;
    int lq = lane >> 2, kq = lane & 3;
    #pragma unroll
    for (int mt = 0; mt < 2; mt++) {
        #pragma unroll
        for (int h = 0; h < 2; h++) {
            int rl = mt_ * 64 + wm * 32 + mt * 16 + lq + h * 8;
            if (rl >= cnt) continue;
            int tok = g_slot_tok[off + rl];
            float w = g_slot_w[off + rl];
            float* dst = dout + (size_t)tok * H_DIM + nb;
            #pragma unroll
            for (int nt = 0; nt < 4; nt++) {
                int c0 = wn * 32 + nt * 8 + 2 * kq;
                atomicAdd(&dst[c0],     w * acc[mt][nt][h * 2]);
                atomicAdd(&dst[c0 + 1], w * acc[mt][nt][h * 2 + 1]);
            }
        }
    }
}

// ---------------- launch ----------------
extern "C" void kernel_launch(void* const* d_in, const int* in_sizes, int n_in,
                              void* d_out, int out_size) {
    const float* x     = (const float*)d_in[0];
    const float* gattn = (const float*)d_in[1];
    const float* wq    = (const float*)d_in[2];
    const float* wk    = (const float*)d_in[3];
    const float* wv    = (const float*)d_in[4];
    const float* wo    = (const float*)d_in[5];
    const float* gffn  = (const float*)d_in[6];
    const float* wr    = (const float*)d_in[7];
    const float* w1    = (const float*)d_in[8];
    const float* w2    = (const float*)d_in[9];
    float* out = (float*)d_out;
    int write_aux = (out_size > T_TOK * H_DIM) ? 1 : 0;

    reset_kernel<<<1, 32>>>();

    rmsnorm_kernel<<<T_TOK, 256>>>(x, gattn, 0);
    {
        dim3 g(H_DIM / 64, T_TOK / 64, 3);
        gemm_qkv_kernel<<<g, 128>>>(wq, wk, wv);
    }
    {
        int nthr = T_TOK * N_HEAD * 32;
        rope_kernel<<<(nthr + 255) / 256, 256>>>();
    }
    {
        dim3 g(SEQ / 64, N_HEAD, BATCH);
        flash_kernel<<<g, 64>>>();
    }
    {
        dim3 g(H_DIM / 64, T_TOK / 64);
        gemm_wo_kernel<<<g, 128>>>(x, wo, out);
    }

    rmsnorm_kernel<<<T_TOK, 256>>>(x, gffn, 1);
    router_kernel<<<T_TOK / 4, 128>>>(wr);
    scan_kernel<<<1, 32>>>(out, write_aux);
    fill_kernel<<<(T_TOK * 2 + 255) / 256, 256>>>();
    {
        dim3 g(F_DIM / 64, T_TOK / 64, N_EXP);
        moe_gemm1_kernel<<<g, 128>>>(w1);
    }
    {
        dim3 g(H_DIM / 64, T_TOK / 64, N_EXP);
        moe_gemm2_kernel<<<g, 128>>>(w2, out);
    }
}

// round 10
// speedup vs baseline: 2.6173x; 1.2070x over previous
#include <cuda_runtime.h>
#include <math.h>
#include <stdint.h>

#define T_TOK   4096
#define H_DIM   1024
#define N_HEAD  16
#define HEAD_D  64
#define SEQ     1024
#define BATCH   4
#define F_DIM   4096
#define N_EXP   8
#define N_SLOTS (T_TOK * 2)

// GEMM tiling
#define BM 128
#define BN 64
#define BK 16
#define ASTR 20   // As row stride in floats (banks 4m+k conflict-free)
#define BSTR 72   // Bs row stride in floats

// ---------------- scratch ----------------
__device__ float g_xn[T_TOK * H_DIM];
__device__ float g_q[T_TOK * H_DIM];
__device__ float g_k[T_TOK * H_DIM];
__device__ float g_v[T_TOK * H_DIM];
__device__ float g_ao[T_TOK * H_DIM];
__device__ float g_x1[T_TOK * H_DIM];
__device__ float g_h1[(size_t)N_SLOTS * F_DIM];
__device__ float g_zero[F_DIM];            // zero-initialized: padded-row source
__device__ int   g_cnt[N_EXP];
__device__ int   g_fill[N_EXP];
__device__ int   g_off[N_EXP];
__device__ float g_psum[N_EXP];
__device__ int   g_topi[T_TOK * 2];
__device__ float g_topw[T_TOK * 2];
__device__ int   g_slot_tok[N_SLOTS];
__device__ float g_slot_w[N_SLOTS];

// ---------------- helpers ----------------
__device__ __forceinline__ float gelu_tanh(float x) {
    float x3 = x * x * x;
    return 0.5f * x * (1.0f + tanhf(0.7978845608028654f * (x + 0.044715f * x3)));
}

__device__ __forceinline__ void mma_tf32(float (&c)[4], const uint32_t (&a)[4],
                                         const uint32_t (&b)[2]) {
    asm volatile(
        "mma.sync.aligned.m16n8k8.row.col.f32.tf32.tf32.f32 "
        "{%0,%1,%2,%3}, {%4,%5,%6,%7}, {%8,%9}, {%0,%1,%2,%3};"
        : "+f"(c[0]), "+f"(c[1]), "+f"(c[2]), "+f"(c[3])
        : "r"(a[0]), "r"(a[1]), "r"(a[2]), "r"(a[3]), "r"(b[0]), "r"(b[1]));
}

__device__ __forceinline__ void cp16(uint32_t dst, const void* src) {
    asm volatile("cp.async.cg.shared.global [%0], [%1], 16;"
                 :: "r"(dst), "l"(src));
}
__device__ __forceinline__ void cp_commit() { asm volatile("cp.async.commit_group;"); }
__device__ __forceinline__ void cp_wait0()  { asm volatile("cp.async.wait_group 0;"); }

// ---------------- reset ----------------
__global__ void reset_kernel() {
    int i = threadIdx.x;
    if (i < N_EXP) { g_cnt[i] = 0; g_fill[i] = 0; g_psum[i] = 0.f; }
}

// ---------------- rmsnorm ----------------
__global__ void rmsnorm_kernel(const float* __restrict__ xin,
                               const float* __restrict__ gamma,
                               int use_x1) {
    int t = blockIdx.x;
    const float* src = use_x1 ? (const float*)g_x1 : xin;
    const float4* xr = (const float4*)(src + (size_t)t * H_DIM);
    int tid = threadIdx.x;
    float4 v = xr[tid];
    float ss = v.x * v.x + v.y * v.y + v.z * v.z + v.w * v.w;
    int lane = tid & 31, wid = tid >> 5;
    #pragma unroll
    for (int o = 16; o > 0; o >>= 1) ss += __shfl_down_sync(0xffffffffu, ss, o);
    __shared__ float red[8];
    if (lane == 0) red[wid] = ss;
    __syncthreads();
    if (tid == 0) {
        float tot = 0.f;
        #pragma unroll
        for (int i = 0; i < 8; i++) tot += red[i];
        red[0] = rsqrtf(tot / (float)H_DIM + 1e-5f);
    }
    __syncthreads();
    float r = red[0];
    float4 g = ((const float4*)gamma)[tid];
    float4 out;
    out.x = v.x * r * g.x; out.y = v.y * r * g.y;
    out.z = v.z * r * g.z; out.w = v.w * r * g.w;
    ((float4*)(g_xn + (size_t)t * H_DIM))[tid] = out;
}

// =====================================================================
// tf32 GEMM core: BM=128 x BN=64, BK=16, 256 threads (8 warps 4x2),
// warp tile 32x32 = 2 m16 x 4 n8 (m16n8k8). Double-buffered smem fed by
// cp.async.cg (constant 16B copies); fp32 bits fed to tf32 MMA directly.
// Padded rows read from g_zero (zero-initialized device global).
// =====================================================================
struct GemmSmem {
    const float* Arow[BM];
    uint32_t As[2][BM][ASTR];
    uint32_t Bs[2][BK][BSTR];
};

__device__ __forceinline__ void stage_load(
    GemmSmem& sm, int st, int k0,
    const float* ap0, int m0,
    const float* ap1, int m1, int c4a,
    const float* __restrict__ B, int ldb, int bk, int bn4)
{
    uint32_t d0 = (uint32_t)__cvta_generic_to_shared(&sm.As[st][m0][c4a]);
    uint32_t d1 = (uint32_t)__cvta_generic_to_shared(&sm.As[st][m1][c4a]);
    uint32_t db = (uint32_t)__cvta_generic_to_shared(&sm.Bs[st][bk][bn4]);
    cp16(d0, ap0 + k0 + c4a);
    cp16(d1, ap1 + k0 + c4a);
    cp16(db, B + (size_t)(k0 + bk) * ldb + bn4);
}

__device__ __forceinline__ void stage_compute(
    GemmSmem& sm, int st, float (&acc)[2][4][4],
    int wm, int wn, int lq, int kq)
{
    #pragma unroll
    for (int ks = 0; ks < 2; ks++) {
        uint32_t a[2][4], b[4][2];
        #pragma unroll
        for (int mt = 0; mt < 2; mt++) {
            int r = wm * 32 + mt * 16 + lq;
            a[mt][0] = sm.As[st][r    ][ks * 8 + kq];
            a[mt][1] = sm.As[st][r + 8][ks * 8 + kq];
            a[mt][2] = sm.As[st][r    ][ks * 8 + kq + 4];
            a[mt][3] = sm.As[st][r + 8][ks * 8 + kq + 4];
        }
        #pragma unroll
        for (int nt = 0; nt < 4; nt++) {
            int c = wn * 32 + nt * 8 + lq;
            b[nt][0] = sm.Bs[st][ks * 8 + kq    ][c];
            b[nt][1] = sm.Bs[st][ks * 8 + kq + 4][c];
        }
        #pragma unroll
        for (int mt = 0; mt < 2; mt++)
            #pragma unroll
            for (int nt = 0; nt < 4; nt++)
                mma_tf32(acc[mt][nt], a[mt], b[nt]);
    }
}

__device__ __forceinline__ void gemm_run(
    GemmSmem& sm, const float* __restrict__ B, int ldb, int K,
    float (&acc)[2][4][4], int tid)
{
    const int m0 = tid >> 2, m1 = m0 + 64, c4a = (tid & 3) * 4;
    const int bk = tid >> 4, bn4 = (tid & 15) * 4;
    const int lane = tid & 31, warp = tid >> 5;
    const int wm = warp >> 1, wn = warp & 1;
    const int lq = lane >> 2, kq = lane & 3;

    const float* ap0 = sm.Arow[m0];
    const float* ap1 = sm.Arow[m1];
    if (!ap0) ap0 = g_zero;
    if (!ap1) ap1 = g_zero;

    stage_load(sm, 0, 0, ap0, m0, ap1, m1, c4a, B, ldb, bk, bn4);
    cp_commit();
    int st = 0;
    for (int k0 = 0; k0 < K; k0 += BK) {
        cp_wait0();
        __syncthreads();
        if (k0 + BK < K) {
            stage_load(sm, st ^ 1, k0 + BK, ap0, m0, ap1, m1, c4a, B, ldb, bk, bn4);
            cp_commit();
        }
        stage_compute(sm, st, acc, wm, wn, lq, kq);
        st ^= 1;
    }
}

// ---------------- QKV projection ----------------
__global__ void gemm_qkv_kernel(const float* __restrict__ wq,
                                const float* __restrict__ wk,
                                const float* __restrict__ wv) {
    __shared__ GemmSmem sm;
    int tid = threadIdx.x;
    int nb = blockIdx.x * BN, mb = blockIdx.y * BM;
    const float* B = (blockIdx.z == 0 ? wq : (blockIdx.z == 1 ? wk : wv)) + nb;
    float* C = (blockIdx.z == 0 ? g_q : (blockIdx.z == 1 ? g_k : g_v));
    if (tid < BM) sm.Arow[tid] = g_xn + (size_t)(mb + tid) * H_DIM;
    __syncthreads();
    float acc[2][4][4] = {};
    gemm_run(sm, B, H_DIM, H_DIM, acc, tid);
    int lane = tid & 31, warp = tid >> 5;
    int wm = warp >> 1, wn = warp & 1;
    int lq = lane >> 2, kq = lane & 3;
    #pragma unroll
    for (int mt = 0; mt < 2; mt++) {
        int r0 = mb + wm * 32 + mt * 16 + lq;
        #pragma unroll
        for (int nt = 0; nt < 4; nt++) {
            int c0 = nb + wn * 32 + nt * 8 + 2 * kq;
            C[(size_t)r0 * H_DIM + c0]           = acc[mt][nt][0];
            C[(size_t)r0 * H_DIM + c0 + 1]       = acc[mt][nt][1];
            C[(size_t)(r0 + 8) * H_DIM + c0]     = acc[mt][nt][2];
            C[(size_t)(r0 + 8) * H_DIM + c0 + 1] = acc[mt][nt][3];
        }
    }
}

// ---------------- RoPE ----------------
__global__ void rope_kernel() {
    int gid = blockIdx.x * blockDim.x + threadIdx.x;
    if (gid >= T_TOK * N_HEAD * 32) return;
    int i = gid & 31;
    int n = (gid >> 5) & 15;
    int t = gid >> 9;
    int s = t & (SEQ - 1);
    float inv = __expf(-9.210340371976184f * ((float)i / 32.0f));
    float ang = (float)s * inv;
    float c = cosf(ang), si = sinf(ang);
    size_t base = (size_t)t * H_DIM + n * HEAD_D;
    {
        float x1 = g_q[base + i], x2 = g_q[base + 32 + i];
        g_q[base + i]      = x1 * c - x2 * si;
        g_q[base + 32 + i] = x2 * c + x1 * si;
    }
    {
        float x1 = g_k[base + i], x2 = g_k[base + 32 + i];
        g_k[base + i]      = x1 * c - x2 * si;
        g_k[base + 32 + i] = x2 * c + x1 * si;
    }
}

// ---------------- flash attention: 128 threads, 2 threads per query row ----------------
// WARP-UNIFORM trip counts: every lane in a warp runs the same number of
// j iterations; causal masking is arithmetic (s = -1e30f), never a break,
// so the __shfl_xor pair-reduction is always convergent.
__global__ void flash_kernel() {
    __shared__ float Ks[64][64];
    __shared__ float Vs[64][64];
    int qt = blockIdx.x, nh = blockIdx.y, b = blockIdx.z;
    int tid = threadIdx.x;                 // 128
    int row = tid >> 1;                    // query row within tile (0..63)
    int half = tid & 1;                    // which 32 dims
    int warp = tid >> 5;                   // warp covers rows 16w..16w+15
    int qrow = qt * 64 + row;
    int t = b * SEQ + qrow;
    float q[32], o[32];
    const float4* qp = (const float4*)(g_q + (size_t)t * H_DIM + nh * HEAD_D + half * 32);
    #pragma unroll
    for (int i = 0; i < 8; i++) {
        float4 v = qp[i];
        q[4 * i] = v.x; q[4 * i + 1] = v.y; q[4 * i + 2] = v.z; q[4 * i + 3] = v.w;
    }
    #pragma unroll
    for (int d = 0; d < 32; d++) o[d] = 0.f;
    float m = -1e30f, l = 0.f;
    for (int kt = 0; kt <= qt; kt++) {
        for (int idx = tid; idx < 64 * 64; idx += 128) {
            int r = idx >> 6, c = idx & 63;
            size_t src = (size_t)(b * SEQ + kt * 64 + r) * H_DIM + nh * HEAD_D + c;
            Ks[r][c] = g_k[src];
            Vs[r][c] = g_v[src];
        }
        __syncthreads();
        // warp-uniform iteration count: full tile off-diagonal; on the
        // diagonal tile, the warp's max row is 16*warp+15 -> limit 16*warp+16.
        int jlim = (kt == qt) ? (warp * 16 + 16) : 64;
        for (int j = 0; j < jlim; j++) {
            int kglob = kt * 64 + j;
            const float* kr = &Ks[j][half * 32];
            float s0 = 0.f, s1 = 0.f, s2 = 0.f, s3 = 0.f;
            #pragma unroll
            for (int d = 0; d < 32; d += 4) {
                s0 += q[d]     * kr[d];
                s1 += q[d + 1] * kr[d + 1];
                s2 += q[d + 2] * kr[d + 2];
                s3 += q[d + 3] * kr[d + 3];
            }
            float part = s0 + s1 + s2 + s3;
            float s = (part + __shfl_xor_sync(0xffffffffu, part, 1)) * 0.125f;
            if (kglob > qrow) s = -1e30f;   // causal mask; j=0 is always valid so m anchors first
            if (s > m) {
                float c = __expf(m - s);
                l *= c;
                #pragma unroll
                for (int d = 0; d < 32; d++) o[d] *= c;
                m = s;
            }
            float p = __expf(s - m);
            l += p;
            const float* vr = &Vs[j][half * 32];
            #pragma unroll
            for (int d = 0; d < 32; d++) o[d] += p * vr[d];
        }
        __syncthreads();
    }
    float invl = 1.0f / l;
    float* op = g_ao + (size_t)t * H_DIM + nh * HEAD_D + half * 32;
    #pragma unroll
    for (int d = 0; d < 32; d++) op[d] = o[d] * invl;
}

// ---------------- WO projection + residual ----------------
__global__ void gemm_wo_kernel(const float* __restrict__ x,
                               const float* __restrict__ wo,
                               float* __restrict__ dout) {
    __shared__ GemmSmem sm;
    int tid = threadIdx.x;
    int nb = blockIdx.x * BN, mb = blockIdx.y * BM;
    if (tid < BM) sm.Arow[tid] = g_ao + (size_t)(mb + tid) * H_DIM;
    __syncthreads();
    float acc[2][4][4] = {};
    gemm_run(sm, wo + nb, H_DIM, H_DIM, acc, tid);
    int lane = tid & 31, warp = tid >> 5;
    int wm = warp >> 1, wn = warp & 1;
    int lq = lane >> 2, kq = lane & 3;
    #pragma unroll
    for (int mt = 0; mt < 2; mt++) {
        int r0 = mb + wm * 32 + mt * 16 + lq;
        #pragma unroll
        for (int nt = 0; nt < 4; nt++) {
            int c0 = nb + wn * 32 + nt * 8 + 2 * kq;
            #pragma unroll
            for (int h = 0; h < 2; h++) {
                size_t i0 = (size_t)(r0 + h * 8) * H_DIM + c0;
                float v0 = x[i0] + acc[mt][nt][h * 2];
                float v1 = x[i0 + 1] + acc[mt][nt][h * 2 + 1];
                g_x1[i0] = v0; g_x1[i0 + 1] = v1;
                dout[i0] = v0; dout[i0 + 1] = v1;
            }
        }
    }
}

// ---------------- router ----------------
__global__ void router_kernel(const float* __restrict__ wr) {
    int warp = (blockIdx.x * blockDim.x + threadIdx.x) >> 5;
    int lane = threadIdx.x & 31;
    if (warp >= T_TOK) return;
    const float* xr = g_xn + (size_t)warp * H_DIM;
    float acc[N_EXP];
    #pragma unroll
    for (int e = 0; e < N_EXP; e++) acc[e] = 0.f;
    for (int h = lane; h < H_DIM; h += 32) {
        float xv = xr[h];
        #pragma unroll
        for (int e = 0; e < N_EXP; e++) acc[e] += xv * wr[h * N_EXP + e];
    }
    #pragma unroll
    for (int e = 0; e < N_EXP; e++)
        #pragma unroll
        for (int o = 16; o > 0; o >>= 1)
            acc[e] += __shfl_down_sync(0xffffffffu, acc[e], o);
    if (lane == 0) {
        float mx = acc[0];
        #pragma unroll
        for (int e = 1; e < N_EXP; e++) mx = fmaxf(mx, acc[e]);
        float p[N_EXP], s = 0.f;
        #pragma unroll
        for (int e = 0; e < N_EXP; e++) { p[e] = expf(acc[e] - mx); s += p[e]; }
        float invs = 1.0f / s;
        #pragma unroll
        for (int e = 0; e < N_EXP; e++) p[e] *= invs;
        int i0 = 0;
        #pragma unroll
        for (int e = 1; e < N_EXP; e++) if (p[e] > p[i0]) i0 = e;
        int i1 = (i0 == 0) ? 1 : 0;
        #pragma unroll
        for (int e = 0; e < N_EXP; e++) if (e != i0 && p[e] > p[i1]) i1 = e;
        float w0 = p[i0], w1 = p[i1];
        float ws = 1.0f / (w0 + w1);
        g_topi[warp * 2] = i0;      g_topi[warp * 2 + 1] = i1;
        g_topw[warp * 2] = w0 * ws; g_topw[warp * 2 + 1] = w1 * ws;
        atomicAdd(&g_cnt[i0], 1);
        atomicAdd(&g_cnt[i1], 1);
        #pragma unroll
        for (int e = 0; e < N_EXP; e++) atomicAdd(&g_psum[e], p[e]);
    }
}

// ---------------- prefix + aux ----------------
__global__ void scan_kernel(float* __restrict__ dout, int write_aux) {
    if (threadIdx.x == 0) {
        int off = 0;
        float aux = 0.f;
        for (int e = 0; e < N_EXP; e++) { g_off[e] = off; off += g_cnt[e]; }
        for (int e = 0; e < N_EXP; e++) {
            float f = (float)g_cnt[e] / (float)(T_TOK * 2);
            float P = g_psum[e] / (float)T_TOK;
            aux += f * P;
        }
        aux *= (float)N_EXP;
        if (write_aux) dout[(size_t)T_TOK * H_DIM] = aux;
    }
}

// ---------------- gather lists ----------------
__global__ void fill_kernel() {
    int gid = blockIdx.x * blockDim.x + threadIdx.x;
    if (gid >= T_TOK * 2) return;
    int t = gid >> 1;
    int e = g_topi[gid];
    int pos = g_off[e] + atomicAdd(&g_fill[e], 1);
    g_slot_tok[pos] = t;
    g_slot_w[pos] = g_topw[gid];
}

// ---------------- MoE GEMM1 ----------------
__global__ void moe_gemm1_kernel(const float* __restrict__ w1) {
    int e = blockIdx.z;
    int cnt = g_cnt[e];
    int mt_ = blockIdx.y;
    if (mt_ * BM >= cnt) return;
    int off = g_off[e];
    __shared__ GemmSmem sm;
    int tid = threadIdx.x;
    if (tid < BM) {
        int rl = mt_ * BM + tid;
        sm.Arow[tid] = (rl < cnt) ? g_xn + (size_t)g_slot_tok[off + rl] * H_DIM : (const float*)0;
    }
    __syncthreads();
    int nb = blockIdx.x * BN;
    const float* B = w1 + (size_t)e * H_DIM * F_DIM + nb;
    float acc[2][4][4] = {};
    gemm_run(sm, B, F_DIM, H_DIM, acc, tid);
    int lane = tid & 31, warp = tid >> 5;
    int wm = warp >> 1, wn = warp & 1;
    int lq = lane >> 2, kq = lane & 3;
    #pragma unroll
    for (int mt = 0; mt < 2; mt++) {
        #pragma unroll
        for (int h = 0; h < 2; h++) {
            int rl = mt_ * BM + wm * 32 + mt * 16 + lq + h * 8;
            if (rl >= cnt) continue;
            float* dst = g_h1 + (size_t)(off + rl) * F_DIM + nb;
            #pragma unroll
            for (int nt = 0; nt < 4; nt++) {
                int c0 = wn * 32 + nt * 8 + 2 * kq;
                dst[c0]     = gelu_tanh(acc[mt][nt][h * 2]);
                dst[c0 + 1] = gelu_tanh(acc[mt][nt][h * 2 + 1]);
            }
        }
    }
}

// ---------------- MoE GEMM2 ----------------
__global__ void moe_gemm2_kernel(const float* __restrict__ w2,
                                 float* __restrict__ dout) {
    int e = blockIdx.z;
    int cnt = g_cnt[e];
    int mt_ = blockIdx.y;
    if (mt_ * BM >= cnt) return;
    int off = g_off[e];
    __shared__ GemmSmem sm;
    int tid = threadIdx.x;
    if (tid < BM) {
        int rl = mt_ * BM + tid;
        sm.Arow[tid] = (rl < cnt) ? g_h1 + (size_t)(off + rl) * F_DIM : (const float*)0;
    }
    __syncthreads();
    int nb = blockIdx.x * BN;
    const float* B = w2 + (size_t)e * F_DIM * H_DIM + nb;
    float acc[2][4][4] = {};
    gemm_run(sm, B, H_DIM, F_DIM, acc, tid);
    int lane = tid & 31, warp = tid >> 5;
    int wm = warp >> 1, wn = warp & 1;
    int lq = lane >> 2, kq = lane & 3;
    #pragma unroll
    for (int mt = 0; mt < 2; mt++) {
        #pragma unroll
        for (int h = 0; h < 2; h++) {
            int rl = mt_ * BM + wm * 32 + mt * 16 + lq + h * 8;
            if (rl >= cnt) continue;
            int tok = g_slot_tok[off + rl];
            float w = g_slot_w[off + rl];
            float* dst = dout + (size_t)tok * H_DIM + nb;
            #pragma unroll
            for (int nt = 0; nt < 4; nt++) {
                int c0 = wn * 32 + nt * 8 + 2 * kq;
                atomicAdd(&dst[c0],     w * acc[mt][nt][h * 2]);
                atomicAdd(&dst[c0 + 1], w * acc[mt][nt][h * 2 + 1]);
            }
        }
    }
}

// ---------------- launch ----------------
extern "C" void kernel_launch(void* const* d_in, const int* in_sizes, int n_in,
                              void* d_out, int out_size) {
    const float* x     = (const float*)d_in[0];
    const float* gattn = (const float*)d_in[1];
    const float* wq    = (const float*)d_in[2];
    const float* wk    = (const float*)d_in[3];
    const float* wv    = (const float*)d_in[4];
    const float* wo    = (const float*)d_in[5];
    const float* gffn  = (const float*)d_in[6];
    const float* wr    = (const float*)d_in[7];
    const float* w1    = (const float*)d_in[8];
    const float* w2    = (const float*)d_in[9];
    float* out = (float*)d_out;
    int write_aux = (out_size > T_TOK * H_DIM) ? 1 : 0;

    reset_kernel<<<1, 32>>>();

    rmsnorm_kernel<<<T_TOK, 256>>>(x, gattn, 0);
    {
        dim3 g(H_DIM / BN, T_TOK / BM, 3);
        gemm_qkv_kernel<<<g, 256>>>(wq, wk, wv);
    }
    {
        int nthr = T_TOK * N_HEAD * 32;
        rope_kernel<<<(nthr + 255) / 256, 256>>>();
    }
    {
        dim3 g(SEQ / 64, N_HEAD, BATCH);
        flash_kernel<<<g, 128>>>();
    }
    {
        dim3 g(H_DIM / BN, T_TOK / BM);
        gemm_wo_kernel<<<g, 256>>>(x, wo, out);
    }

    rmsnorm_kernel<<<T_TOK, 256>>>(x, gffn, 1);
    router_kernel<<<T_TOK / 4, 128>>>(wr);
    scan_kernel<<<1, 32>>>(out, write_aux);
    fill_kernel<<<(T_TOK * 2 + 255) / 256, 256>>>();
    {
        dim3 g(F_DIM / BN, T_TOK / BM, N_EXP);
        moe_gemm1_kernel<<<g, 256>>>(w1);
    }
    {
        dim3 g(H_DIM / BN, T_TOK / BM, N_EXP);
        moe_gemm2_kernel<<<g, 256>>>(w2, out);
    }
}

// round 11
// speedup vs baseline: 2.7129x; 1.0365x over previous
#include <cuda_runtime.h>
#include <math.h>
#include <stdint.h>

#define T_TOK   4096
#define H_DIM   1024
#define N_HEAD  16
#define HEAD_D  64
#define SEQ     1024
#define BATCH   4
#define F_DIM   4096
#define N_EXP   8
#define N_SLOTS (T_TOK * 2)

// GEMM tiling: 128x128 block tile, BK=16, 256 threads (8 warps, 4x2)
#define BM 128
#define BN 128
#define BK 16
#define ASTR 20    // As row stride in floats: (lq*20+kq) mod 32 covers all banks
#define BSTR 136   // Bs row stride: 136 mod 32 = 8 -> conflict-free (kq*8+lq+nt*8)

// ---------------- scratch ----------------
__device__ float g_xn[T_TOK * H_DIM];
__device__ float g_q[T_TOK * H_DIM];
__device__ float g_k[T_TOK * H_DIM];
__device__ float g_v[T_TOK * H_DIM];
__device__ float g_ao[T_TOK * H_DIM];
__device__ float g_x1[T_TOK * H_DIM];
__device__ float g_h1[(size_t)N_SLOTS * F_DIM];
__device__ float g_zero[F_DIM];            // zero-initialized: padded-row source
__device__ int   g_cnt[N_EXP];
__device__ int   g_fill[N_EXP];
__device__ int   g_off[N_EXP];
__device__ float g_psum[N_EXP];
__device__ int   g_topi[T_TOK * 2];
__device__ float g_topw[T_TOK * 2];
__device__ int   g_slot_tok[N_SLOTS];
__device__ float g_slot_w[N_SLOTS];

// ---------------- helpers ----------------
__device__ __forceinline__ float gelu_tanh(float x) {
    float x3 = x * x * x;
    return 0.5f * x * (1.0f + tanhf(0.7978845608028654f * (x + 0.044715f * x3)));
}

__device__ __forceinline__ void mma_tf32(float (&c)[4], const uint32_t (&a)[4],
                                         const uint32_t (&b)[2]) {
    asm volatile(
        "mma.sync.aligned.m16n8k8.row.col.f32.tf32.tf32.f32 "
        "{%0,%1,%2,%3}, {%4,%5,%6,%7}, {%8,%9}, {%0,%1,%2,%3};"
        : "+f"(c[0]), "+f"(c[1]), "+f"(c[2]), "+f"(c[3])
        : "r"(a[0]), "r"(a[1]), "r"(a[2]), "r"(a[3]), "r"(b[0]), "r"(b[1]));
}

__device__ __forceinline__ void cp16(uint32_t dst, const void* src) {
    asm volatile("cp.async.cg.shared.global [%0], [%1], 16;"
                 :: "r"(dst), "l"(src));
}
__device__ __forceinline__ void cp_commit() { asm volatile("cp.async.commit_group;"); }
__device__ __forceinline__ void cp_wait0()  { asm volatile("cp.async.wait_group 0;"); }

// ---------------- reset ----------------
__global__ void reset_kernel() {
    int i = threadIdx.x;
    if (i < N_EXP) { g_cnt[i] = 0; g_fill[i] = 0; g_psum[i] = 0.f; }
}

// ---------------- rmsnorm ----------------
__global__ void rmsnorm_kernel(const float* __restrict__ xin,
                               const float* __restrict__ gamma,
                               int use_x1) {
    int t = blockIdx.x;
    const float* src = use_x1 ? (const float*)g_x1 : xin;
    const float4* xr = (const float4*)(src + (size_t)t * H_DIM);
    int tid = threadIdx.x;
    float4 v = xr[tid];
    float ss = v.x * v.x + v.y * v.y + v.z * v.z + v.w * v.w;
    int lane = tid & 31, wid = tid >> 5;
    #pragma unroll
    for (int o = 16; o > 0; o >>= 1) ss += __shfl_down_sync(0xffffffffu, ss, o);
    __shared__ float red[8];
    if (lane == 0) red[wid] = ss;
    __syncthreads();
    if (tid == 0) {
        float tot = 0.f;
        #pragma unroll
        for (int i = 0; i < 8; i++) tot += red[i];
        red[0] = rsqrtf(tot / (float)H_DIM + 1e-5f);
    }
    __syncthreads();
    float r = red[0];
    float4 g = ((const float4*)gamma)[tid];
    float4 out;
    out.x = v.x * r * g.x; out.y = v.y * r * g.y;
    out.z = v.z * r * g.z; out.w = v.w * r * g.w;
    ((float4*)(g_xn + (size_t)t * H_DIM))[tid] = out;
}

// =====================================================================
// tf32 GEMM core: BM=128 x BN=128, BK=16, 256 threads, 8 warps (4x2).
// Warp tile 32x64 = 2 m16 x 8 n8 (m16n8k8), acc[2][8][4].
// Double-buffered smem fed by cp.async.cg; raw fp32 bits -> tf32 MMA.
// =====================================================================
struct GemmSmem {
    const float* Arow[BM];
    uint32_t As[2][BM][ASTR];
    uint32_t Bs[2][BK][BSTR];
};

__device__ __forceinline__ void stage_load(
    GemmSmem& sm, int st, int k0,
    const float* ap, int ar, int ac,
    const float* __restrict__ B, int ldb, int bk, int bn)
{
    uint32_t da0 = (uint32_t)__cvta_generic_to_shared(&sm.As[st][ar][ac]);
    uint32_t da1 = (uint32_t)__cvta_generic_to_shared(&sm.As[st][ar][ac + 4]);
    uint32_t db0 = (uint32_t)__cvta_generic_to_shared(&sm.Bs[st][bk][bn]);
    uint32_t db1 = (uint32_t)__cvta_generic_to_shared(&sm.Bs[st][bk][bn + 4]);
    const float* bsrc = B + (size_t)(k0 + bk) * ldb + bn;
    cp16(da0, ap + k0 + ac);
    cp16(da1, ap + k0 + ac + 4);
    cp16(db0, bsrc);
    cp16(db1, bsrc + 4);
}

__device__ __forceinline__ void stage_compute(
    GemmSmem& sm, int st, float (&acc)[2][8][4],
    int wm, int wn, int lq, int kq)
{
    #pragma unroll
    for (int ks = 0; ks < 2; ks++) {
        uint32_t a[2][4], b[8][2];
        #pragma unroll
        for (int mt = 0; mt < 2; mt++) {
            int r = wm * 32 + mt * 16 + lq;
            a[mt][0] = sm.As[st][r    ][ks * 8 + kq];
            a[mt][1] = sm.As[st][r + 8][ks * 8 + kq];
            a[mt][2] = sm.As[st][r    ][ks * 8 + kq + 4];
            a[mt][3] = sm.As[st][r + 8][ks * 8 + kq + 4];
        }
        #pragma unroll
        for (int nt = 0; nt < 8; nt++) {
            int c = wn * 64 + nt * 8 + lq;
            b[nt][0] = sm.Bs[st][ks * 8 + kq    ][c];
            b[nt][1] = sm.Bs[st][ks * 8 + kq + 4][c];
        }
        #pragma unroll
        for (int mt = 0; mt < 2; mt++)
            #pragma unroll
            for (int nt = 0; nt < 8; nt++)
                mma_tf32(acc[mt][nt], a[mt], b[nt]);
    }
}

__device__ __forceinline__ void gemm_run(
    GemmSmem& sm, const float* __restrict__ B, int ldb, int K,
    float (&acc)[2][8][4], int tid)
{
    const int ar = tid >> 1, ac = (tid & 1) * 8;   // A: 128 rows x 16 (8 floats/thread half)
    const int bk = tid >> 4, bn = (tid & 15) * 8;  // B: 16 rows x 128
    const int lane = tid & 31, warp = tid >> 5;
    const int wm = warp >> 1, wn = warp & 1;
    const int lq = lane >> 2, kq = lane & 3;

    const float* ap = sm.Arow[ar];
    if (!ap) ap = g_zero;

    stage_load(sm, 0, 0, ap, ar, ac, B, ldb, bk, bn);
    cp_commit();
    int st = 0;
    for (int k0 = 0; k0 < K; k0 += BK) {
        cp_wait0();
        __syncthreads();
        if (k0 + BK < K) {
            stage_load(sm, st ^ 1, k0 + BK, ap, ar, ac, B, ldb, bk, bn);
            cp_commit();
        }
        stage_compute(sm, st, acc, wm, wn, lq, kq);
        st ^= 1;
    }
}

// ---------------- QKV projection ----------------
__global__ void gemm_qkv_kernel(const float* __restrict__ wq,
                                const float* __restrict__ wk,
                                const float* __restrict__ wv) {
    __shared__ GemmSmem sm;
    int tid = threadIdx.x;
    int nb = blockIdx.x * BN, mb = blockIdx.y * BM;
    const float* B = (blockIdx.z == 0 ? wq : (blockIdx.z == 1 ? wk : wv)) + nb;
    float* C = (blockIdx.z == 0 ? g_q : (blockIdx.z == 1 ? g_k : g_v));
    if (tid < BM) sm.Arow[tid] = g_xn + (size_t)(mb + tid) * H_DIM;
    __syncthreads();
    float acc[2][8][4] = {};
    gemm_run(sm, B, H_DIM, H_DIM, acc, tid);
    int lane = tid & 31, warp = tid >> 5;
    int wm = warp >> 1, wn = warp & 1;
    int lq = lane >> 2, kq = lane & 3;
    #pragma unroll
    for (int mt = 0; mt < 2; mt++) {
        int r0 = mb + wm * 32 + mt * 16 + lq;
        #pragma unroll
        for (int nt = 0; nt < 8; nt++) {
            int c0 = nb + wn * 64 + nt * 8 + 2 * kq;
            C[(size_t)r0 * H_DIM + c0]           = acc[mt][nt][0];
            C[(size_t)r0 * H_DIM + c0 + 1]       = acc[mt][nt][1];
            C[(size_t)(r0 + 8) * H_DIM + c0]     = acc[mt][nt][2];
            C[(size_t)(r0 + 8) * H_DIM + c0 + 1] = acc[mt][nt][3];
        }
    }
}

// ---------------- RoPE ----------------
__global__ void rope_kernel() {
    int gid = blockIdx.x * blockDim.x + threadIdx.x;
    if (gid >= T_TOK * N_HEAD * 32) return;
    int i = gid & 31;
    int n = (gid >> 5) & 15;
    int t = gid >> 9;
    int s = t & (SEQ - 1);
    float inv = __expf(-9.210340371976184f * ((float)i / 32.0f));
    float ang = (float)s * inv;
    float c = cosf(ang), si = sinf(ang);
    size_t base = (size_t)t * H_DIM + n * HEAD_D;
    {
        float x1 = g_q[base + i], x2 = g_q[base + 32 + i];
        g_q[base + i]      = x1 * c - x2 * si;
        g_q[base + 32 + i] = x2 * c + x1 * si;
    }
    {
        float x1 = g_k[base + i], x2 = g_k[base + 32 + i];
        g_k[base + i]      = x1 * c - x2 * si;
        g_k[base + 32 + i] = x2 * c + x1 * si;
    }
}

// ---------------- flash attention: 128 threads, 2 threads per query row ----------------
// Warp-uniform trip counts; causal mask is arithmetic, never a break.
__global__ void flash_kernel() {
    __shared__ float Ks[64][64];
    __shared__ float Vs[64][64];
    int qt = blockIdx.x, nh = blockIdx.y, b = blockIdx.z;
    int tid = threadIdx.x;                 // 128
    int row = tid >> 1;                    // query row within tile (0..63)
    int half = tid & 1;                    // which 32 dims
    int warp = tid >> 5;                   // warp covers rows 16w..16w+15
    int qrow = qt * 64 + row;
    int t = b * SEQ + qrow;
    float q[32], o[32];
    const float4* qp = (const float4*)(g_q + (size_t)t * H_DIM + nh * HEAD_D + half * 32);
    #pragma unroll
    for (int i = 0; i < 8; i++) {
        float4 v = qp[i];
        q[4 * i] = v.x; q[4 * i + 1] = v.y; q[4 * i + 2] = v.z; q[4 * i + 3] = v.w;
    }
    #pragma unroll
    for (int d = 0; d < 32; d++) o[d] = 0.f;
    float m = -1e30f, l = 0.f;
    for (int kt = 0; kt <= qt; kt++) {
        for (int idx = tid; idx < 64 * 64; idx += 128) {
            int r = idx >> 6, c = idx & 63;
            size_t src = (size_t)(b * SEQ + kt * 64 + r) * H_DIM + nh * HEAD_D + c;
            Ks[r][c] = g_k[src];
            Vs[r][c] = g_v[src];
        }
        __syncthreads();
        int jlim = (kt == qt) ? (warp * 16 + 16) : 64;
        for (int j = 0; j < jlim; j++) {
            int kglob = kt * 64 + j;
            const float* kr = &Ks[j][half * 32];
            float s0 = 0.f, s1 = 0.f, s2 = 0.f, s3 = 0.f;
            #pragma unroll
            for (int d = 0; d < 32; d += 4) {
                s0 += q[d]     * kr[d];
                s1 += q[d + 1] * kr[d + 1];
                s2 += q[d + 2] * kr[d + 2];
                s3 += q[d + 3] * kr[d + 3];
            }
            float part = s0 + s1 + s2 + s3;
            float s = (part + __shfl_xor_sync(0xffffffffu, part, 1)) * 0.125f;
            if (kglob > qrow) s = -1e30f;
            if (s > m) {
                float c = __expf(m - s);
                l *= c;
                #pragma unroll
                for (int d = 0; d < 32; d++) o[d] *= c;
                m = s;
            }
            float p = __expf(s - m);
            l += p;
            const float* vr = &Vs[j][half * 32];
            #pragma unroll
            for (int d = 0; d < 32; d++) o[d] += p * vr[d];
        }
        __syncthreads();
    }
    float invl = 1.0f / l;
    float* op = g_ao + (size_t)t * H_DIM + nh * HEAD_D + half * 32;
    #pragma unroll
    for (int d = 0; d < 32; d++) op[d] = o[d] * invl;
}

// ---------------- WO projection + residual ----------------
__global__ void gemm_wo_kernel(const float* __restrict__ x,
                               const float* __restrict__ wo,
                               float* __restrict__ dout) {
    __shared__ GemmSmem sm;
    int tid = threadIdx.x;
    int nb = blockIdx.x * BN, mb = blockIdx.y * BM;
    if (tid < BM) sm.Arow[tid] = g_ao + (size_t)(mb + tid) * H_DIM;
    __syncthreads();
    float acc[2][8][4] = {};
    gemm_run(sm, wo + nb, H_DIM, H_DIM, acc, tid);
    int lane = tid & 31, warp = tid >> 5;
    int wm = warp >> 1, wn = warp & 1;
    int lq = lane >> 2, kq = lane & 3;
    #pragma unroll
    for (int mt = 0; mt < 2; mt++) {
        int r0 = mb + wm * 32 + mt * 16 + lq;
        #pragma unroll
        for (int nt = 0; nt < 8; nt++) {
            int c0 = nb + wn * 64 + nt * 8 + 2 * kq;
            #pragma unroll
            for (int h = 0; h < 2; h++) {
                size_t i0 = (size_t)(r0 + h * 8) * H_DIM + c0;
                float v0 = x[i0] + acc[mt][nt][h * 2];
                float v1 = x[i0 + 1] + acc[mt][nt][h * 2 + 1];
                g_x1[i0] = v0; g_x1[i0 + 1] = v1;
                dout[i0] = v0; dout[i0 + 1] = v1;
            }
        }
    }
}

// ---------------- router ----------------
__global__ void router_kernel(const float* __restrict__ wr) {
    int warp = (blockIdx.x * blockDim.x + threadIdx.x) >> 5;
    int lane = threadIdx.x & 31;
    if (warp >= T_TOK) return;
    const float* xr = g_xn + (size_t)warp * H_DIM;
    float acc[N_EXP];
    #pragma unroll
    for (int e = 0; e < N_EXP; e++) acc[e] = 0.f;
    for (int h = lane; h < H_DIM; h += 32) {
        float xv = xr[h];
        #pragma unroll
        for (int e = 0; e < N_EXP; e++) acc[e] += xv * wr[h * N_EXP + e];
    }
    #pragma unroll
    for (int e = 0; e < N_EXP; e++)
        #pragma unroll
        for (int o = 16; o > 0; o >>= 1)
            acc[e] += __shfl_down_sync(0xffffffffu, acc[e], o);
    if (lane == 0) {
        float mx = acc[0];
        #pragma unroll
        for (int e = 1; e < N_EXP; e++) mx = fmaxf(mx, acc[e]);
        float p[N_EXP], s = 0.f;
        #pragma unroll
        for (int e = 0; e < N_EXP; e++) { p[e] = expf(acc[e] - mx); s += p[e]; }
        float invs = 1.0f / s;
        #pragma unroll
        for (int e = 0; e < N_EXP; e++) p[e] *= invs;
        int i0 = 0;
        #pragma unroll
        for (int e = 1; e < N_EXP; e++) if (p[e] > p[i0]) i0 = e;
        int i1 = (i0 == 0) ? 1 : 0;
        #pragma unroll
        for (int e = 0; e < N_EXP; e++) if (e != i0 && p[e] > p[i1]) i1 = e;
        float w0 = p[i0], w1 = p[i1];
        float ws = 1.0f / (w0 + w1);
        g_topi[warp * 2] = i0;      g_topi[warp * 2 + 1] = i1;
        g_topw[warp * 2] = w0 * ws; g_topw[warp * 2 + 1] = w1 * ws;
        atomicAdd(&g_cnt[i0], 1);
        atomicAdd(&g_cnt[i1], 1);
        #pragma unroll
        for (int e = 0; e < N_EXP; e++) atomicAdd(&g_psum[e], p[e]);
    }
}

// ---------------- prefix + aux ----------------
__global__ void scan_kernel(float* __restrict__ dout, int write_aux) {
    if (threadIdx.x == 0) {
        int off = 0;
        float aux = 0.f;
        for (int e = 0; e < N_EXP; e++) { g_off[e] = off; off += g_cnt[e]; }
        for (int e = 0; e < N_EXP; e++) {
            float f = (float)g_cnt[e] / (float)(T_TOK * 2);
            float P = g_psum[e] / (float)T_TOK;
            aux += f * P;
        }
        aux *= (float)N_EXP;
        if (write_aux) dout[(size_t)T_TOK * H_DIM] = aux;
    }
}

// ---------------- gather lists ----------------
__global__ void fill_kernel() {
    int gid = blockIdx.x * blockDim.x + threadIdx.x;
    if (gid >= T_TOK * 2) return;
    int t = gid >> 1;
    int e = g_topi[gid];
    int pos = g_off[e] + atomicAdd(&g_fill[e], 1);
    g_slot_tok[pos] = t;
    g_slot_w[pos] = g_topw[gid];
}

// ---------------- MoE GEMM1 ----------------
__global__ void moe_gemm1_kernel(const float* __restrict__ w1) {
    int e = blockIdx.z;
    int cnt = g_cnt[e];
    int mt_ = blockIdx.y;
    if (mt_ * BM >= cnt) return;
    int off = g_off[e];
    __shared__ GemmSmem sm;
    int tid = threadIdx.x;
    if (tid < BM) {
        int rl = mt_ * BM + tid;
        sm.Arow[tid] = (rl < cnt) ? g_xn + (size_t)g_slot_tok[off + rl] * H_DIM : (const float*)0;
    }
    __syncthreads();
    int nb = blockIdx.x * BN;
    const float* B = w1 + (size_t)e * H_DIM * F_DIM + nb;
    float acc[2][8][4] = {};
    gemm_run(sm, B, F_DIM, H_DIM, acc, tid);
    int lane = tid & 31, warp = tid >> 5;
    int wm = warp >> 1, wn = warp & 1;
    int lq = lane >> 2, kq = lane & 3;
    #pragma unroll
    for (int mt = 0; mt < 2; mt++) {
        #pragma unroll
        for (int h = 0; h < 2; h++) {
            int rl = mt_ * BM + wm * 32 + mt * 16 + lq + h * 8;
            if (rl >= cnt) continue;
            float* dst = g_h1 + (size_t)(off + rl) * F_DIM + nb;
            #pragma unroll
            for (int nt = 0; nt < 8; nt++) {
                int c0 = wn * 64 + nt * 8 + 2 * kq;
                dst[c0]     = gelu_tanh(acc[mt][nt][h * 2]);
                dst[c0 + 1] = gelu_tanh(acc[mt][nt][h * 2 + 1]);
            }
        }
    }
}

// ---------------- MoE GEMM2 ----------------
__global__ void moe_gemm2_kernel(const float* __restrict__ w2,
                                 float* __restrict__ dout) {
    int e = blockIdx.z;
    int cnt = g_cnt[e];
    int mt_ = blockIdx.y;
    if (mt_ * BM >= cnt) return;
    int off = g_off[e];
    __shared__ GemmSmem sm;
    int tid = threadIdx.x;
    if (tid < BM) {
        int rl = mt_ * BM + tid;
        sm.Arow[tid] = (rl < cnt) ? g_h1 + (size_t)(off + rl) * F_DIM : (const float*)0;
    }
    __syncthreads();
    int nb = blockIdx.x * BN;
    const float* B = w2 + (size_t)e * F_DIM * H_DIM + nb;
    float acc[2][8][4] = {};
    gemm_run(sm, B, H_DIM, F_DIM, acc, tid);
    int lane = tid & 31, warp = tid >> 5;
    int wm = warp >> 1, wn = warp & 1;
    int lq = lane >> 2, kq = lane & 3;
    #pragma unroll
    for (int mt = 0; mt < 2; mt++) {
        #pragma unroll
        for (int h = 0; h < 2; h++) {
            int rl = mt_ * BM + wm * 32 + mt * 16 + lq + h * 8;
            if (rl >= cnt) continue;
            int tok = g_slot_tok[off + rl];
            float w = g_slot_w[off + rl];
            float* dst = dout + (size_t)tok * H_DIM + nb;
            #pragma unroll
            for (int nt = 0; nt < 8; nt++) {
                int c0 = wn * 64 + nt * 8 + 2 * kq;
                atomicAdd(&dst[c0],     w * acc[mt][nt][h * 2]);
                atomicAdd(&dst[c0 + 1], w * acc[mt][nt][h * 2 + 1]);
            }
        }
    }
}

// ---------------- launch ----------------
extern "C" void kernel_launch(void* const* d_in, const int* in_sizes, int n_in,
                              void* d_out, int out_size) {
    const float* x     = (const float*)d_in[0];
    const float* gattn = (const float*)d_in[1];
    const float* wq    = (const float*)d_in[2];
    const float* wk    = (const float*)d_in[3];
    const float* wv    = (const float*)d_in[4];
    const float* wo    = (const float*)d_in[5];
    const float* gffn  = (const float*)d_in[6];
    const float* wr    = (const float*)d_in[7];
    const float* w1    = (const float*)d_in[8];
    const float* w2    = (const float*)d_in[9];
    float* out = (float*)d_out;
    int write_aux = (out_size > T_TOK * H_DIM) ? 1 : 0;

    reset_kernel<<<1, 32>>>();

    rmsnorm_kernel<<<T_TOK, 256>>>(x, gattn, 0);
    {
        dim3 g(H_DIM / BN, T_TOK / BM, 3);
        gemm_qkv_kernel<<<g, 256>>>(wq, wk, wv);
    }
    {
        int nthr = T_TOK * N_HEAD * 32;
        rope_kernel<<<(nthr + 255) / 256, 256>>>();
    }
    {
        dim3 g(SEQ / 64, N_HEAD, BATCH);
        flash_kernel<<<g, 128>>>();
    }
    {
        dim3 g(H_DIM / BN, T_TOK / BM);
        gemm_wo_kernel<<<g, 256>>>(x, wo, out);
    }

    rmsnorm_kernel<<<T_TOK, 256>>>(x, gffn, 1);
    router_kernel<<<T_TOK / 4, 128>>>(wr);
    scan_kernel<<<1, 32>>>(out, write_aux);
    fill_kernel<<<(T_TOK * 2 + 255) / 256, 256>>>();
    {
        dim3 g(F_DIM / BN, T_TOK / BM, N_EXP);
        moe_gemm1_kernel<<<g, 256>>>(w1);
    }
    {
        dim3 g(H_DIM / BN, T_TOK / BM, N_EXP);
        moe_gemm2_kernel<<<g, 256>>>(w2, out);
    }
}

// round 13
// speedup vs baseline: 2.7149x; 1.0008x over previous
#include <cuda_runtime.h>
#include <math.h>
#include <stdint.h>

#define T_TOK   4096
#define H_DIM   1024
#define N_HEAD  16
#define HEAD_D  64
#define SEQ     1024
#define BATCH   4
#define F_DIM   4096
#define N_EXP   8
#define N_SLOTS (T_TOK * 2)

// GEMM tiling: 128x128 block tile, BK=16, 256 threads (8 warps, 4x2)
#define BM 128
#define BN 128
#define BK 16
#define ASTR 20    // As row stride in floats: (lq*20+kq) mod 32 covers all banks
#define BSTR 136   // Bs row stride: 136 mod 32 = 8 -> conflict-free (kq*8+lq+nt*8)

// ---------------- scratch ----------------
__device__ float g_xn[T_TOK * H_DIM];
__device__ float g_q[T_TOK * H_DIM];
__device__ float g_k[T_TOK * H_DIM];
__device__ float g_v[T_TOK * H_DIM];
__device__ float g_ao[T_TOK * H_DIM];
__device__ float g_x1[T_TOK * H_DIM];
__device__ float g_h1[(size_t)N_SLOTS * F_DIM];
__device__ float g_zero[F_DIM];            // zero-initialized: padded-row source
__device__ int   g_cnt[N_EXP];
__device__ int   g_fill[N_EXP];
__device__ int   g_off[N_EXP];
__device__ float g_psum[N_EXP];
__device__ int   g_topi[T_TOK * 2];
__device__ float g_topw[T_TOK * 2];
__device__ int   g_slot_tok[N_SLOTS];
__device__ float g_slot_w[N_SLOTS];

// ---------------- helpers ----------------
__device__ __forceinline__ float gelu_tanh(float x) {
    float x3 = x * x * x;
    return 0.5f * x * (1.0f + tanhf(0.7978845608028654f * (x + 0.044715f * x3)));
}

__device__ __forceinline__ void mma_tf32(float (&c)[4], const uint32_t (&a)[4],
                                         const uint32_t (&b)[2]) {
    asm volatile(
        "mma.sync.aligned.m16n8k8.row.col.f32.tf32.tf32.f32 "
        "{%0,%1,%2,%3}, {%4,%5,%6,%7}, {%8,%9}, {%0,%1,%2,%3};"
        : "+f"(c[0]), "+f"(c[1]), "+f"(c[2]), "+f"(c[3])
        : "r"(a[0]), "r"(a[1]), "r"(a[2]), "r"(a[3]), "r"(b[0]), "r"(b[1]));
}

__device__ __forceinline__ void cp16(uint32_t dst, const void* src) {
    asm volatile("cp.async.cg.shared.global [%0], [%1], 16;"
                 :: "r"(dst), "l"(src));
}
__device__ __forceinline__ void cp_commit() { asm volatile("cp.async.commit_group;"); }
__device__ __forceinline__ void cp_wait0()  { asm volatile("cp.async.wait_group 0;"); }

// ---------------- reset ----------------
__global__ void reset_kernel() {
    int i = threadIdx.x;
    if (i < N_EXP) { g_cnt[i] = 0; g_fill[i] = 0; g_psum[i] = 0.f; }
}

// ---------------- rmsnorm ----------------
__global__ void rmsnorm_kernel(const float* __restrict__ xin,
                               const float* __restrict__ gamma,
                               int use_x1) {
    int t = blockIdx.x;
    const float* src = use_x1 ? (const float*)g_x1 : xin;
    const float4* xr = (const float4*)(src + (size_t)t * H_DIM);
    int tid = threadIdx.x;
    float4 v = xr[tid];
    float ss = v.x * v.x + v.y * v.y + v.z * v.z + v.w * v.w;
    int lane = tid & 31, wid = tid >> 5;
    #pragma unroll
    for (int o = 16; o > 0; o >>= 1) ss += __shfl_down_sync(0xffffffffu, ss, o);
    __shared__ float red[8];
    if (lane == 0) red[wid] = ss;
    __syncthreads();
    if (tid == 0) {
        float tot = 0.f;
        #pragma unroll
        for (int i = 0; i < 8; i++) tot += red[i];
        red[0] = rsqrtf(tot / (float)H_DIM + 1e-5f);
    }
    __syncthreads();
    float r = red[0];
    float4 g = ((const float4*)gamma)[tid];
    float4 out;
    out.x = v.x * r * g.x; out.y = v.y * r * g.y;
    out.z = v.z * r * g.z; out.w = v.w * r * g.w;
    ((float4*)(g_xn + (size_t)t * H_DIM))[tid] = out;
}

// =====================================================================
// tf32 GEMM core: BM=128 x BN=128, BK=16, 256 threads, 8 warps (4x2).
// Warp tile 32x64 = 2 m16 x 8 n8 (m16n8k8), acc[2][8][4].
// Double-buffered smem fed by cp.async.cg; raw fp32 bits -> tf32 MMA.
// =====================================================================
struct GemmSmem {
    const float* Arow[BM];
    uint32_t As[2][BM][ASTR];
    uint32_t Bs[2][BK][BSTR];
};

__device__ __forceinline__ void stage_load(
    GemmSmem& sm, int st, int k0,
    const float* ap, int ar, int ac,
    const float* __restrict__ B, int ldb, int bk, int bn)
{
    uint32_t da0 = (uint32_t)__cvta_generic_to_shared(&sm.As[st][ar][ac]);
    uint32_t da1 = (uint32_t)__cvta_generic_to_shared(&sm.As[st][ar][ac + 4]);
    uint32_t db0 = (uint32_t)__cvta_generic_to_shared(&sm.Bs[st][bk][bn]);
    uint32_t db1 = (uint32_t)__cvta_generic_to_shared(&sm.Bs[st][bk][bn + 4]);
    const float* bsrc = B + (size_t)(k0 + bk) * ldb + bn;
    cp16(da0, ap + k0 + ac);
    cp16(da1, ap + k0 + ac + 4);
    cp16(db0, bsrc);
    cp16(db1, bsrc + 4);
}

__device__ __forceinline__ void stage_compute(
    GemmSmem& sm, int st, float (&acc)[2][8][4],
    int wm, int wn, int lq, int kq)
{
    #pragma unroll
    for (int ks = 0; ks < 2; ks++) {
        uint32_t a[2][4], b[8][2];
        #pragma unroll
        for (int mt = 0; mt < 2; mt++) {
            int r = wm * 32 + mt * 16 + lq;
            a[mt][0] = sm.As[st][r    ][ks * 8 + kq];
            a[mt][1] = sm.As[st][r + 8][ks * 8 + kq];
            a[mt][2] = sm.As[st][r    ][ks * 8 + kq + 4];
            a[mt][3] = sm.As[st][r + 8][ks * 8 + kq + 4];
        }
        #pragma unroll
        for (int nt = 0; nt < 8; nt++) {
            int c = wn * 64 + nt * 8 + lq;
            b[nt][0] = sm.Bs[st][ks * 8 + kq    ][c];
            b[nt][1] = sm.Bs[st][ks * 8 + kq + 4][c];
        }
        #pragma unroll
        for (int mt = 0; mt < 2; mt++)
            #pragma unroll
            for (int nt = 0; nt < 8; nt++)
                mma_tf32(acc[mt][nt], a[mt], b[nt]);
    }
}

__device__ __forceinline__ void gemm_run(
    GemmSmem& sm, const float* __restrict__ B, int ldb, int K,
    float (&acc)[2][8][4], int tid)
{
    const int ar = tid >> 1, ac = (tid & 1) * 8;   // A: 128 rows x 16 (8 floats/thread half)
    const int bk = tid >> 4, bn = (tid & 15) * 8;  // B: 16 rows x 128
    const int lane = tid & 31, warp = tid >> 5;
    const int wm = warp >> 1, wn = warp & 1;
    const int lq = lane >> 2, kq = lane & 3;

    const float* ap = sm.Arow[ar];
    if (!ap) ap = g_zero;

    stage_load(sm, 0, 0, ap, ar, ac, B, ldb, bk, bn);
    cp_commit();
    int st = 0;
    for (int k0 = 0; k0 < K; k0 += BK) {
        cp_wait0();
        __syncthreads();
        if (k0 + BK < K) {
            stage_load(sm, st ^ 1, k0 + BK, ap, ar, ac, B, ldb, bk, bn);
            cp_commit();
        }
        stage_compute(sm, st, acc, wm, wn, lq, kq);
        st ^= 1;
    }
}

// ---------------- QKV projection ----------------
__global__ void gemm_qkv_kernel(const float* __restrict__ wq,
                                const float* __restrict__ wk,
                                const float* __restrict__ wv) {
    __shared__ GemmSmem sm;
    int tid = threadIdx.x;
    int nb = blockIdx.x * BN, mb = blockIdx.y * BM;
    const float* B = (blockIdx.z == 0 ? wq : (blockIdx.z == 1 ? wk : wv)) + nb;
    float* C = (blockIdx.z == 0 ? g_q : (blockIdx.z == 1 ? g_k : g_v));
    if (tid < BM) sm.Arow[tid] = g_xn + (size_t)(mb + tid) * H_DIM;
    __syncthreads();
    float acc[2][8][4] = {};
    gemm_run(sm, B, H_DIM, H_DIM, acc, tid);
    int lane = tid & 31, warp = tid >> 5;
    int wm = warp >> 1, wn = warp & 1;
    int lq = lane >> 2, kq = lane & 3;
    #pragma unroll
    for (int mt = 0; mt < 2; mt++) {
        int r0 = mb + wm * 32 + mt * 16 + lq;
        #pragma unroll
        for (int nt = 0; nt < 8; nt++) {
            int c0 = nb + wn * 64 + nt * 8 + 2 * kq;
            C[(size_t)r0 * H_DIM + c0]           = acc[mt][nt][0];
            C[(size_t)r0 * H_DIM + c0 + 1]       = acc[mt][nt][1];
            C[(size_t)(r0 + 8) * H_DIM + c0]     = acc[mt][nt][2];
            C[(size_t)(r0 + 8) * H_DIM + c0 + 1] = acc[mt][nt][3];
        }
    }
}

// ---------------- RoPE ----------------
__global__ void rope_kernel() {
    int gid = blockIdx.x * blockDim.x + threadIdx.x;
    if (gid >= T_TOK * N_HEAD * 32) return;
    int i = gid & 31;
    int n = (gid >> 5) & 15;
    int t = gid >> 9;
    int s = t & (SEQ - 1);
    float inv = __expf(-9.210340371976184f * ((float)i / 32.0f));
    float ang = (float)s * inv;
    float c = cosf(ang), si = sinf(ang);
    size_t base = (size_t)t * H_DIM + n * HEAD_D;
    {
        float x1 = g_q[base + i], x2 = g_q[base + 32 + i];
        g_q[base + i]      = x1 * c - x2 * si;
        g_q[base + 32 + i] = x2 * c + x1 * si;
    }
    {
        float x1 = g_k[base + i], x2 = g_k[base + 32 + i];
        g_k[base + i]      = x1 * c - x2 * si;
        g_k[base + 32 + i] = x2 * c + x1 * si;
    }
}

// ---------------- flash attention: 128 threads, 2 threads per query row ----------------
// Warp-uniform trip counts; causal mask is arithmetic, never a break.
__global__ void flash_kernel() {
    __shared__ float Ks[64][64];
    __shared__ float Vs[64][64];
    int qt = blockIdx.x, nh = blockIdx.y, b = blockIdx.z;
    int tid = threadIdx.x;                 // 128
    int row = tid >> 1;                    // query row within tile (0..63)
    int half = tid & 1;                    // which 32 dims
    int warp = tid >> 5;                   // warp covers rows 16w..16w+15
    int qrow = qt * 64 + row;
    int t = b * SEQ + qrow;
    float q[32], o[32];
    const float4* qp = (const float4*)(g_q + (size_t)t * H_DIM + nh * HEAD_D + half * 32);
    #pragma unroll
    for (int i = 0; i < 8; i++) {
        float4 v = qp[i];
        q[4 * i] = v.x; q[4 * i + 1] = v.y; q[4 * i + 2] = v.z; q[4 * i + 3] = v.w;
    }
    #pragma unroll
    for (int d = 0; d < 32; d++) o[d] = 0.f;
    float m = -1e30f, l = 0.f;
    for (int kt = 0; kt <= qt; kt++) {
        for (int idx = tid; idx < 64 * 64; idx += 128) {
            int r = idx >> 6, c = idx & 63;
            size_t src = (size_t)(b * SEQ + kt * 64 + r) * H_DIM + nh * HEAD_D + c;
            Ks[r][c] = g_k[src];
            Vs[r][c] = g_v[src];
        }
        __syncthreads();
        int jlim = (kt == qt) ? (warp * 16 + 16) : 64;
        for (int j = 0; j < jlim; j++) {
            int kglob = kt * 64 + j;
            const float* kr = &Ks[j][half * 32];
            float s0 = 0.f, s1 = 0.f, s2 = 0.f, s3 = 0.f;
            #pragma unroll
            for (int d = 0; d < 32; d += 4) {
                s0 += q[d]     * kr[d];
                s1 += q[d + 1] * kr[d + 1];
                s2 += q[d + 2] * kr[d + 2];
                s3 += q[d + 3] * kr[d + 3];
            }
            float part = s0 + s1 + s2 + s3;
            float s = (part + __shfl_xor_sync(0xffffffffu, part, 1)) * 0.125f;
            if (kglob > qrow) s = -1e30f;
            if (s > m) {
                float c = __expf(m - s);
                l *= c;
                #pragma unroll
                for (int d = 0; d < 32; d++) o[d] *= c;
                m = s;
            }
            float p = __expf(s - m);
            l += p;
            const float* vr = &Vs[j][half * 32];
            #pragma unroll
            for (int d = 0; d < 32; d++) o[d] += p * vr[d];
        }
        __syncthreads();
    }
    float invl = 1.0f / l;
    float* op = g_ao + (size_t)t * H_DIM + nh * HEAD_D + half * 32;
    #pragma unroll
    for (int d = 0; d < 32; d++) op[d] = o[d] * invl;
}

// ---------------- WO projection + residual ----------------
__global__ void gemm_wo_kernel(const float* __restrict__ x,
                               const float* __restrict__ wo,
                               float* __restrict__ dout) {
    __shared__ GemmSmem sm;
    int tid = threadIdx.x;
    int nb = blockIdx.x * BN, mb = blockIdx.y * BM;
    if (tid < BM) sm.Arow[tid] = g_ao + (size_t)(mb + tid) * H_DIM;
    __syncthreads();
    float acc[2][8][4] = {};
    gemm_run(sm, wo + nb, H_DIM, H_DIM, acc, tid);
    int lane = tid & 31, warp = tid >> 5;
    int wm = warp >> 1, wn = warp & 1;
    int lq = lane >> 2, kq = lane & 3;
    #pragma unroll
    for (int mt = 0; mt < 2; mt++) {
        int r0 = mb + wm * 32 + mt * 16 + lq;
        #pragma unroll
        for (int nt = 0; nt < 8; nt++) {
            int c0 = nb + wn * 64 + nt * 8 + 2 * kq;
            #pragma unroll
            for (int h = 0; h < 2; h++) {
                size_t i0 = (size_t)(r0 + h * 8) * H_DIM + c0;
                float v0 = x[i0] + acc[mt][nt][h * 2];
                float v1 = x[i0 + 1] + acc[mt][nt][h * 2 + 1];
                g_x1[i0] = v0; g_x1[i0 + 1] = v1;
                dout[i0] = v0; dout[i0 + 1] = v1;
            }
        }
    }
}

// ---------------- router ----------------
__global__ void router_kernel(const float* __restrict__ wr) {
    int warp = (blockIdx.x * blockDim.x + threadIdx.x) >> 5;
    int lane = threadIdx.x & 31;
    if (warp >= T_TOK) return;
    const float* xr = g_xn + (size_t)warp * H_DIM;
    float acc[N_EXP];
    #pragma unroll
    for (int e = 0; e < N_EXP; e++) acc[e] = 0.f;
    for (int h = lane; h < H_DIM; h += 32) {
        float xv = xr[h];
        #pragma unroll
        for (int e = 0; e < N_EXP; e++) acc[e] += xv * wr[h * N_EXP + e];
    }
    #pragma unroll
    for (int e = 0; e < N_EXP; e++)
        #pragma unroll
        for (int o = 16; o > 0; o >>= 1)
            acc[e] += __shfl_down_sync(0xffffffffu, acc[e], o);
    if (lane == 0) {
        float mx = acc[0];
        #pragma unroll
        for (int e = 1; e < N_EXP; e++) mx = fmaxf(mx, acc[e]);
        float p[N_EXP], s = 0.f;
        #pragma unroll
        for (int e = 0; e < N_EXP; e++) { p[e] = expf(acc[e] - mx); s += p[e]; }
        float invs = 1.0f / s;
        #pragma unroll
        for (int e = 0; e < N_EXP; e++) p[e] *= invs;
        int i0 = 0;
        #pragma unroll
        for (int e = 1; e < N_EXP; e++) if (p[e] > p[i0]) i0 = e;
        int i1 = (i0 == 0) ? 1 : 0;
        #pragma unroll
        for (int e = 0; e < N_EXP; e++) if (e != i0 && p[e] > p[i1]) i1 = e;
        float w0 = p[i0], w1 = p[i1];
        float ws = 1.0f / (w0 + w1);
        g_topi[warp * 2] = i0;      g_topi[warp * 2 + 1] = i1;
        g_topw[warp * 2] = w0 * ws; g_topw[warp * 2 + 1] = w1 * ws;
        atomicAdd(&g_cnt[i0], 1);
        atomicAdd(&g_cnt[i1], 1);
        #pragma unroll
        for (int e = 0; e < N_EXP; e++) atomicAdd(&g_psum[e], p[e]);
    }
}

// ---------------- prefix + aux ----------------
__global__ void scan_kernel(float* __restrict__ dout, int write_aux) {
    if (threadIdx.x == 0) {
        int off = 0;
        float aux = 0.f;
        for (int e = 0; e < N_EXP; e++) { g_off[e] = off; off += g_cnt[e]; }
        for (int e = 0; e < N_EXP; e++) {
            float f = (float)g_cnt[e] / (float)(T_TOK * 2);
            float P = g_psum[e] / (float)T_TOK;
            aux += f * P;
        }
        aux *= (float)N_EXP;
        if (write_aux) dout[(size_t)T_TOK * H_DIM] = aux;
    }
}

// ---------------- gather lists ----------------
__global__ void fill_kernel() {
    int gid = blockIdx.x * blockDim.x + threadIdx.x;
    if (gid >= T_TOK * 2) return;
    int t = gid >> 1;
    int e = g_topi[gid];
    int pos = g_off[e] + atomicAdd(&g_fill[e], 1);
    g_slot_tok[pos] = t;
    g_slot_w[pos] = g_topw[gid];
}

// ---------------- MoE GEMM1 ----------------
__global__ void moe_gemm1_kernel(const float* __restrict__ w1) {
    int e = blockIdx.z;
    int cnt = g_cnt[e];
    int mt_ = blockIdx.y;
    if (mt_ * BM >= cnt) return;
    int off = g_off[e];
    __shared__ GemmSmem sm;
    int tid = threadIdx.x;
    if (tid < BM) {
        int rl = mt_ * BM + tid;
        sm.Arow[tid] = (rl < cnt) ? g_xn + (size_t)g_slot_tok[off + rl] * H_DIM : (const float*)0;
    }
    __syncthreads();
    int nb = blockIdx.x * BN;
    const float* B = w1 + (size_t)e * H_DIM * F_DIM + nb;
    float acc[2][8][4] = {};
    gemm_run(sm, B, F_DIM, H_DIM, acc, tid);
    int lane = tid & 31, warp = tid >> 5;
    int wm = warp >> 1, wn = warp & 1;
    int lq = lane >> 2, kq = lane & 3;
    #pragma unroll
    for (int mt = 0; mt < 2; mt++) {
        #pragma unroll
        for (int h = 0; h < 2; h++) {
            int rl = mt_ * BM + wm * 32 + mt * 16 + lq + h * 8;
            if (rl >= cnt) continue;
            float* dst = g_h1 + (size_t)(off + rl) * F_DIM + nb;
            #pragma unroll
            for (int nt = 0; nt < 8; nt++) {
                int c0 = wn * 64 + nt * 8 + 2 * kq;
                dst[c0]     = gelu_tanh(acc[mt][nt][h * 2]);
                dst[c0 + 1] = gelu_tanh(acc[mt][nt][h * 2 + 1]);
            }
        }
    }
}

// ---------------- MoE GEMM2 ----------------
__global__ void moe_gemm2_kernel(const float* __restrict__ w2,
                                 float* __restrict__ dout) {
    int e = blockIdx.z;
    int cnt = g_cnt[e];
    int mt_ = blockIdx.y;
    if (mt_ * BM >= cnt) return;
    int off = g_off[e];
    __shared__ GemmSmem sm;
    int tid = threadIdx.x;
    if (tid < BM) {
        int rl = mt_ * BM + tid;
        sm.Arow[tid] = (rl < cnt) ? g_h1 + (size_t)(off + rl) * F_DIM : (const float*)0;
    }
    __syncthreads();
    int nb = blockIdx.x * BN;
    const float* B = w2 + (size_t)e * F_DIM * H_DIM + nb;
    float acc[2][8][4] = {};
    gemm_run(sm, B, H_DIM, F_DIM, acc, tid);
    int lane = tid & 31, warp = tid >> 5;
    int wm = warp >> 1, wn = warp & 1;
    int lq = lane >> 2, kq = lane & 3;
    #pragma unroll
    for (int mt = 0; mt < 2; mt++) {
        #pragma unroll
        for (int h = 0; h < 2; h++) {
            int rl = mt_ * BM + wm * 32 + mt * 16 + lq + h * 8;
            if (rl >= cnt) continue;
            int tok = g_slot_tok[off + rl];
            float w = g_slot_w[off + rl];
            float* dst = dout + (size_t)tok * H_DIM + nb;
            #pragma unroll
            for (int nt = 0; nt < 8; nt++) {
                int c0 = wn * 64 + nt * 8 + 2 * kq;
                atomicAdd(&dst[c0],     w * acc[mt][nt][h * 2]);
                atomicAdd(&dst[c0 + 1], w * acc[mt][nt][h * 2 + 1]);
            }
        }
    }
}

// ---------------- launch ----------------
extern "C" void kernel_launch(void* const* d_in, const int* in_sizes, int n_in,
                              void* d_out, int out_size) {
    const float* x     = (const float*)d_in[0];
    const float* gattn = (const float*)d_in[1];
    const float* wq    = (const float*)d_in[2];
    const float* wk    = (const float*)d_in[3];
    const float* wv    = (const float*)d_in[4];
    const float* wo    = (const float*)d_in[5];
    const float* gffn  = (const float*)d_in[6];
    const float* wr    = (const float*)d_in[7];
    const float* w1    = (const float*)d_in[8];
    const float* w2    = (const float*)d_in[9];
    float* out = (float*)d_out;
    int write_aux = (out_size > T_TOK * H_DIM) ? 1 : 0;

    reset_kernel<<<1, 32>>>();

    rmsnorm_kernel<<<T_TOK, 256>>>(x, gattn, 0);
    {
        dim3 g(H_DIM / BN, T_TOK / BM, 3);
        gemm_qkv_kernel<<<g, 256>>>(wq, wk, wv);
    }
    {
        int nthr = T_TOK * N_HEAD * 32;
        rope_kernel<<<(nthr + 255) / 256, 256>>>();
    }
    {
        dim3 g(SEQ / 64, N_HEAD, BATCH);
        flash_kernel<<<g, 128>>>();
    }
    {
        dim3 g(H_DIM / BN, T_TOK / BM);
        gemm_wo_kernel<<<g, 256>>>(x, wo, out);
    }

    rmsnorm_kernel<<<T_TOK, 256>>>(x, gffn, 1);
    router_kernel<<<T_TOK / 4, 128>>>(wr);
    scan_kernel<<<1, 32>>>(out, write_aux);
    fill_kernel<<<(T_TOK * 2 + 255) / 256, 256>>>();
    {
        dim3 g(F_DIM / BN, T_TOK / BM, N_EXP);
        moe_gemm1_kernel<<<g, 256>>>(w1);
    }
    {
        dim3 g(H_DIM / BN, T_TOK / BM, N_EXP);
        moe_gemm2_kernel<<<g, 256>>>(w2, out);
    }
}